// round 10
// baseline (speedup 1.0000x reference)
#include <cuda_runtime.h>
#include <cuda_bf16.h>
#include <cuda_fp16.h>
#include <stdint.h>

// Problem constants
#define B_   2
#define N_   2048
#define E_   1024
#define H_   16
#define HD_  64
#define M_TOT  (B_ * N_)     // 4096
#define QKV_N  (3 * E_)      // 3072
#define BH_    (B_ * H_)     // 32

// ---------------------------------------------------------------------------
// Device scratch (allocation-free rule)
// ---------------------------------------------------------------------------
__device__ __half g_wqkv[(size_t)QKV_N * E_];   // W_qkv^T fp16
__device__ __half g_wout[(size_t)E_ * E_];      // W_out^T fp16
__device__ __half g_xh[(size_t)M_TOT * E_];
__device__ __half g_xl[(size_t)M_TOT * E_];
__device__ __half g_qf[(size_t)BH_ * N_ * HD_]; // [bh][n][d], pre-scaled
__device__ __half g_kf[(size_t)BH_ * N_ * HD_]; // [bh][n][d]
__device__ __half g_vf[(size_t)BH_ * N_ * HD_]; // [bh][n][d] (row-major!)
__device__ __half g_oh[(size_t)M_TOT * E_];     // attn out hi fp16
__device__ __half g_ol[(size_t)M_TOT * E_];     // attn out lo fp16

// ---------------------------------------------------------------------------
// Helpers
// ---------------------------------------------------------------------------
__device__ __forceinline__ uint32_t smem_u32(const void* p) {
    uint32_t a;
    asm("{ .reg .u64 t; cvta.to.shared.u64 t, %1; cvt.u32.u64 %0, t; }"
        : "=r"(a) : "l"(p));
    return a;
}

__device__ __forceinline__ void mma_f16(float c[4], const uint32_t a[4],
                                        const uint32_t b[2]) {
    asm volatile(
        "mma.sync.aligned.m16n8k16.row.col.f32.f16.f16.f32 "
        "{%0,%1,%2,%3},{%4,%5,%6,%7},{%8,%9},{%0,%1,%2,%3};"
        : "+f"(c[0]), "+f"(c[1]), "+f"(c[2]), "+f"(c[3])
        : "r"(a[0]), "r"(a[1]), "r"(a[2]), "r"(a[3]), "r"(b[0]), "r"(b[1]));
}

__device__ __forceinline__ void ldsm4(uint32_t r[4], const void* p) {
    uint32_t a = smem_u32(p);
    asm volatile("ldmatrix.sync.aligned.m8n8.x4.shared.b16 {%0,%1,%2,%3},[%4];"
                 : "=r"(r[0]), "=r"(r[1]), "=r"(r[2]), "=r"(r[3])
                 : "r"(a));
}

__device__ __forceinline__ void ldsm4t(uint32_t r[4], const void* p) {
    uint32_t a = smem_u32(p);
    asm volatile("ldmatrix.sync.aligned.m8n8.x4.trans.shared.b16 {%0,%1,%2,%3},[%4];"
                 : "=r"(r[0]), "=r"(r[1]), "=r"(r[2]), "=r"(r[3])
                 : "r"(a));
}

__device__ __forceinline__ void cpa16(uint32_t s, const void* g) {
    asm volatile("cp.async.cg.shared.global [%0],[%1],16;" ::"r"(s), "l"(g));
}

__device__ __forceinline__ float ex2f(float x) {
    float r;
    asm("ex2.approx.ftz.f32 %0,%1;" : "=f"(r) : "f"(x));
    return r;
}

// Split two floats into packed fp16 hi/lo pairs
__device__ __forceinline__ void split2h(float x, float y, uint32_t& hi, uint32_t& lo) {
    __half xh = __float2half_rn(x);
    __half yh = __float2half_rn(y);
    float xr = x - __half2float(xh);
    float yr = y - __half2float(yh);
    __half2 h2, l2;
    h2.x = xh; h2.y = yh;
    l2.x = __float2half_rn(xr); l2.y = __float2half_rn(yr);
    hi = *reinterpret_cast<uint32_t*>(&h2);
    lo = *reinterpret_cast<uint32_t*>(&l2);
}

// ---------------------------------------------------------------------------
// 1) Elementwise split of x -> fp16 hi/lo
// ---------------------------------------------------------------------------
__global__ void split_x_kernel(const float4* __restrict__ X,
                               __half* __restrict__ Xh,
                               __half* __restrict__ Xl, int n4) {
    int i = blockIdx.x * blockDim.x + threadIdx.x;
    if (i >= n4) return;
    float4 v = X[i];
    uint32_t h0, l0, h1, l1;
    split2h(v.x, v.y, h0, l0);
    split2h(v.z, v.w, h1, l1);
    *(uint32_t*)(Xh + (size_t)i * 4)     = h0;
    *(uint32_t*)(Xh + (size_t)i * 4 + 2) = h1;
    *(uint32_t*)(Xl + (size_t)i * 4)     = l0;
    *(uint32_t*)(Xl + (size_t)i * 4 + 2) = l1;
}

// ---------------------------------------------------------------------------
// 2) Transpose W[K,N] -> Wt fp16 single [N,K]
// ---------------------------------------------------------------------------
__global__ void transpose_f16_kernel(const float* __restrict__ W,
                                     __half* __restrict__ T, int K, int N) {
    __shared__ float t[32][33];
    int k0 = blockIdx.y * 32, n0 = blockIdx.x * 32;
    int tx = threadIdx.x & 31, ty = threadIdx.x >> 5;
#pragma unroll
    for (int i = 0; i < 4; i++)
        t[ty + 8 * i][tx] = W[(size_t)(k0 + ty + 8 * i) * N + n0 + tx];
    __syncthreads();
#pragma unroll
    for (int i = 0; i < 4; i++)
        T[(size_t)(n0 + ty + 8 * i) * K + k0 + tx] = __float2half_rn(t[tx][ty + 8 * i]);
}

// ---------------------------------------------------------------------------
// 3a) Fused QKV GEMM: C = (Ah+Al)@B^T + bias, epilogue writes per-head
//     Q(scaled)/K/V fp16 directly. M=4096, N=3072, K=1024 fixed semantics.
// ---------------------------------------------------------------------------
__global__ __launch_bounds__(256)
void gemm_qkv_fused_kernel(const __half* __restrict__ Ah, const __half* __restrict__ Al,
                           const __half* __restrict__ Bf,
                           const float* __restrict__ bias,
                           __half* __restrict__ Qf, __half* __restrict__ Kf,
                           __half* __restrict__ Vf, int M, int N, int K) {
    __shared__ __half sm[2][3][128][24];  // 36KB; arr: Ah, Al, B
    const int tid = threadIdx.x, lane = tid & 31, w = tid >> 5;
    const int wm = w >> 2, wn = w & 3;    // 2 x 4 warp grid
    const int brow = blockIdx.y * 128, bcol = blockIdx.x * 128;

    float c[4][4][4] = {};

    auto load_stage = [&](int s, int k0) {
#pragma unroll
        for (int i = 0; i < 3; i++) {
            int ch = tid + i * 256;
            int arr = ch >> 8;
            int r = (ch & 255) >> 1;
            int h8 = (ch & 1) * 8;
            const __half* g;
            if (arr == 0)      g = Ah + (size_t)(brow + r) * K + k0 + h8;
            else if (arr == 1) g = Al + (size_t)(brow + r) * K + k0 + h8;
            else               g = Bf + (size_t)(bcol + r) * K + k0 + h8;
            cpa16(smem_u32(&sm[s][arr][r][h8]), g);
        }
        asm volatile("cp.async.commit_group;");
    };

    const int NIT = K >> 4;
    load_stage(0, 0);
    for (int it = 0; it < NIT; ++it) {
        if (it + 1 < NIT) {
            load_stage((it + 1) & 1, (it + 1) * 16);
            asm volatile("cp.async.wait_group 1;");
        } else {
            asm volatile("cp.async.wait_group 0;");
        }
        __syncthreads();
        int s = it & 1;
        uint32_t ah[4][4], al[4][4];
#pragma unroll
        for (int mt = 0; mt < 4; mt++) {
            int row = wm * 64 + mt * 16 + (lane & 15);
            int col = (lane >> 4) * 8;
            ldsm4(ah[mt], &sm[s][0][row][col]);
            ldsm4(al[mt], &sm[s][1][row][col]);
        }
        uint32_t bf[4][2];
#pragma unroll
        for (int p = 0; p < 2; p++) {
            int row = wn * 32 + p * 16 + (lane & 15);
            int col = (lane >> 4) * 8;
            uint32_t t[4];
            ldsm4(t, &sm[s][2][row][col]);
            bf[2 * p][0] = t[0]; bf[2 * p][1] = t[2];
            bf[2 * p + 1][0] = t[1]; bf[2 * p + 1][1] = t[3];
        }
#pragma unroll
        for (int mt = 0; mt < 4; mt++)
#pragma unroll
            for (int nt = 0; nt < 4; nt++) {
                mma_f16(c[mt][nt], ah[mt], bf[nt]);
                mma_f16(c[mt][nt], al[mt], bf[nt]);
            }
        __syncthreads();
    }

    // Fused epilogue: bias, then scatter to Q(scaled)/K/V fp16 [bh][n][64]
    const float qscale = 0.125f * 1.4426950408889634f;  // 1/sqrt(hd) * log2(e)
#pragma unroll
    for (int mt = 0; mt < 4; mt++) {
        int r0 = brow + wm * 64 + mt * 16 + (lane >> 2);
#pragma unroll
        for (int nt = 0; nt < 4; nt++) {
            int col = bcol + wn * 32 + nt * 8 + 2 * (lane & 3);
            int h = col / 192, cc = col % 192;
            float b0 = bias[col], b1 = bias[col + 1];
            __half* dst;
            int d;
            float sc_ = 1.f;
            if (cc < 64)       { dst = Qf; d = cc;       sc_ = qscale; }
            else if (cc < 128) { dst = Kf; d = cc - 64; }
            else               { dst = Vf; d = cc - 128; }
#pragma unroll
            for (int rr = 0; rr < 2; rr++) {
                int row = r0 + rr * 8;
                int b = row >> 11, n = row & 2047;
                float v0 = (c[mt][nt][rr * 2 + 0] + b0) * sc_;
                float v1 = (c[mt][nt][rr * 2 + 1] + b1) * sc_;
                *(__half2*)(dst + ((size_t)((b << 4) + h) * N_ + n) * 64 + d) =
                    __floats2half2_rn(v0, v1);
            }
        }
    }
}

// ---------------------------------------------------------------------------
// 3b) 2-term fp16 GEMM with f32 epilogue (out-projection; R9-proven)
// ---------------------------------------------------------------------------
__global__ __launch_bounds__(256)
void gemm_2t_kernel(const __half* __restrict__ Ah, const __half* __restrict__ Al,
                    const __half* __restrict__ Bf,
                    const float* __restrict__ bias,
                    float* __restrict__ C, int M, int N, int K) {
    __shared__ __half sm[2][3][128][24];
    const int tid = threadIdx.x, lane = tid & 31, w = tid >> 5;
    const int wm = w >> 2, wn = w & 3;
    const int brow = blockIdx.y * 128, bcol = blockIdx.x * 128;

    float c[4][4][4] = {};

    auto load_stage = [&](int s, int k0) {
#pragma unroll
        for (int i = 0; i < 3; i++) {
            int ch = tid + i * 256;
            int arr = ch >> 8;
            int r = (ch & 255) >> 1;
            int h8 = (ch & 1) * 8;
            const __half* g;
            if (arr == 0)      g = Ah + (size_t)(brow + r) * K + k0 + h8;
            else if (arr == 1) g = Al + (size_t)(brow + r) * K + k0 + h8;
            else               g = Bf + (size_t)(bcol + r) * K + k0 + h8;
            cpa16(smem_u32(&sm[s][arr][r][h8]), g);
        }
        asm volatile("cp.async.commit_group;");
    };

    const int NIT = K >> 4;
    load_stage(0, 0);
    for (int it = 0; it < NIT; ++it) {
        if (it + 1 < NIT) {
            load_stage((it + 1) & 1, (it + 1) * 16);
            asm volatile("cp.async.wait_group 1;");
        } else {
            asm volatile("cp.async.wait_group 0;");
        }
        __syncthreads();
        int s = it & 1;
        uint32_t ah[4][4], al[4][4];
#pragma unroll
        for (int mt = 0; mt < 4; mt++) {
            int row = wm * 64 + mt * 16 + (lane & 15);
            int col = (lane >> 4) * 8;
            ldsm4(ah[mt], &sm[s][0][row][col]);
            ldsm4(al[mt], &sm[s][1][row][col]);
        }
        uint32_t bf[4][2];
#pragma unroll
        for (int p = 0; p < 2; p++) {
            int row = wn * 32 + p * 16 + (lane & 15);
            int col = (lane >> 4) * 8;
            uint32_t t[4];
            ldsm4(t, &sm[s][2][row][col]);
            bf[2 * p][0] = t[0]; bf[2 * p][1] = t[2];
            bf[2 * p + 1][0] = t[1]; bf[2 * p + 1][1] = t[3];
        }
#pragma unroll
        for (int mt = 0; mt < 4; mt++)
#pragma unroll
            for (int nt = 0; nt < 4; nt++) {
                mma_f16(c[mt][nt], ah[mt], bf[nt]);
                mma_f16(c[mt][nt], al[mt], bf[nt]);
            }
        __syncthreads();
    }

#pragma unroll
    for (int mt = 0; mt < 4; mt++) {
        int r0 = brow + wm * 64 + mt * 16 + (lane >> 2);
#pragma unroll
        for (int nt = 0; nt < 4; nt++) {
            int col = bcol + wn * 32 + nt * 8 + 2 * (lane & 3);
            float b0 = bias[col], b1 = bias[col + 1];
            float2 v0 = {c[mt][nt][0] + b0, c[mt][nt][1] + b1};
            float2 v1 = {c[mt][nt][2] + b0, c[mt][nt][3] + b1};
            *(float2*)(C + (size_t)r0 * N + col) = v0;
            *(float2*)(C + (size_t)(r0 + 8) * N + col) = v1;
        }
    }
}

// ---------------------------------------------------------------------------
// 4) FA2 attention: single fp16 QK, 2-term PV (P hi/lo x V single).
//    V loaded row-major [key][d], B-fragments via ldmatrix.trans.
// ---------------------------------------------------------------------------
__global__ __launch_bounds__(256)
void attn_kernel(const __half* __restrict__ Qf, const __half* __restrict__ Kf,
                 const __half* __restrict__ Vf,
                 __half* __restrict__ Oh, __half* __restrict__ Ol) {
    __shared__ __half ks[64][72];       // K tile [key][d]
    __shared__ __half vs[64][72];       // V tile [key][d]
    const int tid = threadIdx.x, lane = tid & 31, w = tid >> 5;
    const int bh = blockIdx.y, qb = blockIdx.x;
    const size_t hbase = (size_t)bh * N_ * 64;

    // Q fragments (fp16, pre-scaled) held in registers
    uint32_t qh[4][4];
    {
        int r0 = qb * 128 + w * 16 + (lane >> 2);
        int c0 = 2 * (lane & 3);
#pragma unroll
        for (int kd = 0; kd < 4; kd++) {
            const __half* ph = Qf + hbase + (size_t)r0 * 64 + kd * 16 + c0;
            qh[kd][0] = *(const uint32_t*)(ph);
            qh[kd][1] = *(const uint32_t*)(ph + 8 * 64);
            qh[kd][2] = *(const uint32_t*)(ph + 8);
            qh[kd][3] = *(const uint32_t*)(ph + 8 * 64 + 8);
        }
    }

    float m0 = -1e30f, m1 = -1e30f, l0 = 0.f, l1 = 0.f;
    float o[8][4] = {};

    for (int kt0 = 0; kt0 < N_; kt0 += 64) {
        __syncthreads();
        // Load K + V tiles: 1024 float4 chunks, 4/thread (both row-major)
#pragma unroll
        for (int i = 0; i < 4; i++) {
            int ch = tid + i * 256;
            int arr = ch >> 9;
            int rem = ch & 511;
            int r = rem >> 3;
            int h8 = (rem & 7) * 8;
            if (arr == 0)
                *(float4*)&ks[r][h8] = *(const float4*)(Kf + hbase + (size_t)(kt0 + r) * 64 + h8);
            else
                *(float4*)&vs[r][h8] = *(const float4*)(Vf + hbase + (size_t)(kt0 + r) * 64 + h8);
        }
        __syncthreads();

        // S = Q K^T (single fp16 term, pre-scaled log2 domain)
        float sc[8][4] = {};
#pragma unroll
        for (int kd = 0; kd < 4; kd++) {
            const int colb = kd * 16 + (lane >> 4) * 8;
            uint32_t kb[8][2];
#pragma unroll
            for (int p = 0; p < 4; p++) {
                int row = p * 16 + (lane & 15);
                uint32_t tt[4];
                ldsm4(tt, &ks[row][colb]);
                kb[2 * p][0] = tt[0]; kb[2 * p][1] = tt[2];
                kb[2 * p + 1][0] = tt[1]; kb[2 * p + 1][1] = tt[3];
            }
#pragma unroll
            for (int nt = 0; nt < 8; nt++)
                mma_f16(sc[nt], qh[kd], kb[nt]);
        }

        // Online softmax (base-2)
        float mx0 = -1e30f, mx1 = -1e30f;
#pragma unroll
        for (int nt = 0; nt < 8; nt++) {
            mx0 = fmaxf(mx0, fmaxf(sc[nt][0], sc[nt][1]));
            mx1 = fmaxf(mx1, fmaxf(sc[nt][2], sc[nt][3]));
        }
        mx0 = fmaxf(mx0, __shfl_xor_sync(0xffffffffu, mx0, 1));
        mx0 = fmaxf(mx0, __shfl_xor_sync(0xffffffffu, mx0, 2));
        mx1 = fmaxf(mx1, __shfl_xor_sync(0xffffffffu, mx1, 1));
        mx1 = fmaxf(mx1, __shfl_xor_sync(0xffffffffu, mx1, 2));
        float mn0 = fmaxf(m0, mx0), mn1 = fmaxf(m1, mx1);
        float a0 = ex2f(m0 - mn0), a1 = ex2f(m1 - mn1);
        m0 = mn0; m1 = mn1;

        float sum0 = 0.f, sum1 = 0.f;
#pragma unroll
        for (int nt = 0; nt < 8; nt++) {
            sc[nt][0] = ex2f(sc[nt][0] - mn0);
            sc[nt][1] = ex2f(sc[nt][1] - mn0);
            sc[nt][2] = ex2f(sc[nt][2] - mn1);
            sc[nt][3] = ex2f(sc[nt][3] - mn1);
            sum0 += sc[nt][0] + sc[nt][1];
            sum1 += sc[nt][2] + sc[nt][3];
        }
        sum0 += __shfl_xor_sync(0xffffffffu, sum0, 1);
        sum0 += __shfl_xor_sync(0xffffffffu, sum0, 2);
        sum1 += __shfl_xor_sync(0xffffffffu, sum1, 1);
        sum1 += __shfl_xor_sync(0xffffffffu, sum1, 2);
        l0 = l0 * a0 + sum0;
        l1 = l1 * a1 + sum1;
#pragma unroll
        for (int nd = 0; nd < 8; nd++) {
            o[nd][0] *= a0; o[nd][1] *= a0;
            o[nd][2] *= a1; o[nd][3] *= a1;
        }

        // P fragments, fp16 hi/lo
        uint32_t pah[4][4], pal[4][4];
#pragma unroll
        for (int kt = 0; kt < 4; kt++) {
            split2h(sc[2 * kt][0], sc[2 * kt][1], pah[kt][0], pal[kt][0]);
            split2h(sc[2 * kt][2], sc[2 * kt][3], pah[kt][1], pal[kt][1]);
            split2h(sc[2 * kt + 1][0], sc[2 * kt + 1][1], pah[kt][2], pal[kt][2]);
            split2h(sc[2 * kt + 1][2], sc[2 * kt + 1][3], pah[kt][3], pal[kt][3]);
        }

        // O += P V: B fragments via ldmatrix.trans on V[key][d]
#pragma unroll
        for (int kt = 0; kt < 4; kt++) {
            uint32_t vb[8][2];
#pragma unroll
            for (int p = 0; p < 4; p++) {
                int krow = kt * 16 + (lane & 15);
                int dcol = p * 16 + (lane >> 4) * 8;
                uint32_t tt[4];
                ldsm4t(tt, &vs[krow][dcol]);
                vb[2 * p][0] = tt[0];     vb[2 * p][1] = tt[1];
                vb[2 * p + 1][0] = tt[2]; vb[2 * p + 1][1] = tt[3];
            }
#pragma unroll
            for (int nd = 0; nd < 8; nd++) {
                mma_f16(o[nd], pah[kt], vb[nd]);
                mma_f16(o[nd], pal[kt], vb[nd]);
            }
        }
    }

    // Epilogue: normalize, split to fp16 hi/lo for out-projection
    float i0 = 1.f / l0, i1 = 1.f / l1;
    int b = bh >> 4, h = bh & 15;
    int r0 = b * N_ + qb * 128 + w * 16 + (lane >> 2);
#pragma unroll
    for (int nd = 0; nd < 8; nd++) {
        int col = h * 64 + nd * 8 + 2 * (lane & 3);
        uint32_t hi, lo;
        split2h(o[nd][0] * i0, o[nd][1] * i0, hi, lo);
        *(uint32_t*)(Oh + (size_t)r0 * E_ + col) = hi;
        *(uint32_t*)(Ol + (size_t)r0 * E_ + col) = lo;
        split2h(o[nd][2] * i1, o[nd][3] * i1, hi, lo);
        *(uint32_t*)(Oh + (size_t)(r0 + 8) * E_ + col) = hi;
        *(uint32_t*)(Ol + (size_t)(r0 + 8) * E_ + col) = lo;
    }
}

// ---------------------------------------------------------------------------
extern "C" void kernel_launch(void* const* d_in, const int* in_sizes, int n_in,
                              void* d_out, int out_size) {
    (void)in_sizes; (void)n_in; (void)out_size;
    const float* x     = (const float*)d_in[0];
    const float* W_qkv = (const float*)d_in[1];
    const float* b_qkv = (const float*)d_in[2];
    const float* W_out = (const float*)d_in[3];
    const float* b_out = (const float*)d_in[4];
    float* out = (float*)d_out;

    __half *wq, *wo, *xh, *xl, *q_f, *k_f, *v_f, *o_h, *o_l;
    cudaGetSymbolAddress((void**)&wq, g_wqkv);
    cudaGetSymbolAddress((void**)&wo, g_wout);
    cudaGetSymbolAddress((void**)&xh, g_xh);
    cudaGetSymbolAddress((void**)&xl, g_xl);
    cudaGetSymbolAddress((void**)&q_f, g_qf);
    cudaGetSymbolAddress((void**)&k_f, g_kf);
    cudaGetSymbolAddress((void**)&v_f, g_vf);
    cudaGetSymbolAddress((void**)&o_h, g_oh);
    cudaGetSymbolAddress((void**)&o_l, g_ol);

    // Prep: split x (fp16 hi/lo), transpose both weights to fp16
    split_x_kernel<<<(M_TOT * E_ / 4 + 255) / 256, 256>>>((const float4*)x, xh, xl,
                                                          M_TOT * E_ / 4);
    transpose_f16_kernel<<<dim3(QKV_N / 32, E_ / 32), 256>>>(W_qkv, wq, E_, QKV_N);
    transpose_f16_kernel<<<dim3(E_ / 32, E_ / 32), 256>>>(W_out, wo, E_, E_);

    // QKV projection with fused repack epilogue
    gemm_qkv_fused_kernel<<<dim3(QKV_N / 128, M_TOT / 128), 256>>>(
        xh, xl, wq, b_qkv, q_f, k_f, v_f, M_TOT, QKV_N, E_);

    // Attention
    attn_kernel<<<dim3(N_ / 128, BH_), 256>>>(q_f, k_f, v_f, o_h, o_l);

    // Output projection (2-term fp16)
    gemm_2t_kernel<<<dim3(E_ / 128, M_TOT / 128), 256>>>(
        o_h, o_l, wo, b_out, out, M_TOT, E_, E_);
}

// round 11
// speedup vs baseline: 1.5144x; 1.5144x over previous
#include <cuda_runtime.h>
#include <cuda_bf16.h>
#include <cuda_fp16.h>
#include <stdint.h>

// Problem constants
#define B_   2
#define N_   2048
#define E_   1024
#define H_   16
#define HD_  64
#define M_TOT  (B_ * N_)     // 4096
#define QKV_N  (3 * E_)      // 3072
#define BH_    (B_ * H_)     // 32

// ---------------------------------------------------------------------------
// Device scratch (allocation-free rule)
// ---------------------------------------------------------------------------
__device__ __half g_wqkv[(size_t)QKV_N * E_];   // W_qkv^T fp16
__device__ __half g_wout[(size_t)E_ * E_];      // W_out^T fp16
__device__ __half g_xh[(size_t)M_TOT * E_];
__device__ __half g_xl[(size_t)M_TOT * E_];
__device__ float g_qkv[(size_t)M_TOT * QKV_N];
__device__ __half g_qf[(size_t)BH_ * N_ * HD_];
__device__ __half g_kf[(size_t)BH_ * N_ * HD_];
__device__ __half g_vt[(size_t)BH_ * HD_ * N_];
__device__ __half g_oh[(size_t)M_TOT * E_];     // attn out hi fp16
__device__ __half g_ol[(size_t)M_TOT * E_];     // attn out lo fp16

// ---------------------------------------------------------------------------
// Helpers
// ---------------------------------------------------------------------------
__device__ __forceinline__ uint32_t smem_u32(const void* p) {
    uint32_t a;
    asm("{ .reg .u64 t; cvta.to.shared.u64 t, %1; cvt.u32.u64 %0, t; }"
        : "=r"(a) : "l"(p));
    return a;
}

__device__ __forceinline__ void mma_f16(float c[4], const uint32_t a[4],
                                        const uint32_t b[2]) {
    asm volatile(
        "mma.sync.aligned.m16n8k16.row.col.f32.f16.f16.f32 "
        "{%0,%1,%2,%3},{%4,%5,%6,%7},{%8,%9},{%0,%1,%2,%3};"
        : "+f"(c[0]), "+f"(c[1]), "+f"(c[2]), "+f"(c[3])
        : "r"(a[0]), "r"(a[1]), "r"(a[2]), "r"(a[3]), "r"(b[0]), "r"(b[1]));
}

__device__ __forceinline__ void ldsm4(uint32_t r[4], const void* p) {
    uint32_t a = smem_u32(p);
    asm volatile("ldmatrix.sync.aligned.m8n8.x4.shared.b16 {%0,%1,%2,%3},[%4];"
                 : "=r"(r[0]), "=r"(r[1]), "=r"(r[2]), "=r"(r[3])
                 : "r"(a));
}

__device__ __forceinline__ void cpa16(uint32_t s, const void* g) {
    asm volatile("cp.async.cg.shared.global [%0],[%1],16;" ::"r"(s), "l"(g));
}

__device__ __forceinline__ float ex2f(float x) {
    float r;
    asm("ex2.approx.ftz.f32 %0,%1;" : "=f"(r) : "f"(x));
    return r;
}

// Split two floats into packed fp16 hi/lo pairs
__device__ __forceinline__ void split2h(float x, float y, uint32_t& hi, uint32_t& lo) {
    __half xh = __float2half_rn(x);
    __half yh = __float2half_rn(y);
    float xr = x - __half2float(xh);
    float yr = y - __half2float(yh);
    __half2 h2, l2;
    h2.x = xh; h2.y = yh;
    l2.x = __float2half_rn(xr); l2.y = __float2half_rn(yr);
    hi = *reinterpret_cast<uint32_t*>(&h2);
    lo = *reinterpret_cast<uint32_t*>(&l2);
}

// ---------------------------------------------------------------------------
// 1) Elementwise split of x -> fp16 hi/lo
// ---------------------------------------------------------------------------
__global__ void split_x_kernel(const float4* __restrict__ X,
                               __half* __restrict__ Xh,
                               __half* __restrict__ Xl, int n4) {
    int i = blockIdx.x * blockDim.x + threadIdx.x;
    if (i >= n4) return;
    float4 v = X[i];
    uint32_t h0, l0, h1, l1;
    split2h(v.x, v.y, h0, l0);
    split2h(v.z, v.w, h1, l1);
    *(uint32_t*)(Xh + (size_t)i * 4)     = h0;
    *(uint32_t*)(Xh + (size_t)i * 4 + 2) = h1;
    *(uint32_t*)(Xl + (size_t)i * 4)     = l0;
    *(uint32_t*)(Xl + (size_t)i * 4 + 2) = l1;
}

// ---------------------------------------------------------------------------
// 2) Transpose W[K,N] -> Wt fp16 single [N,K]
// ---------------------------------------------------------------------------
__global__ void transpose_f16_kernel(const float* __restrict__ W,
                                     __half* __restrict__ T, int K, int N) {
    __shared__ float t[32][33];
    int k0 = blockIdx.y * 32, n0 = blockIdx.x * 32;
    int tx = threadIdx.x & 31, ty = threadIdx.x >> 5;
#pragma unroll
    for (int i = 0; i < 4; i++)
        t[ty + 8 * i][tx] = W[(size_t)(k0 + ty + 8 * i) * N + n0 + tx];
    __syncthreads();
#pragma unroll
    for (int i = 0; i < 4; i++)
        T[(size_t)(n0 + ty + 8 * i) * K + k0 + tx] = __float2half_rn(t[tx][ty + 8 * i]);
}

// ---------------------------------------------------------------------------
// 3) 2-term fp16 GEMM, f32 output (R9-proven): C = (Ah+Al)@B^T + bias
// ---------------------------------------------------------------------------
__global__ __launch_bounds__(256)
void gemm_2t_kernel(const __half* __restrict__ Ah, const __half* __restrict__ Al,
                    const __half* __restrict__ Bf,
                    const float* __restrict__ bias,
                    float* __restrict__ C, int M, int N, int K) {
    __shared__ __half sm[2][3][128][24];  // 36KB; arr: Ah, Al, B
    const int tid = threadIdx.x, lane = tid & 31, w = tid >> 5;
    const int wm = w >> 2, wn = w & 3;    // 2 x 4 warp grid
    const int brow = blockIdx.y * 128, bcol = blockIdx.x * 128;

    float c[4][4][4] = {};

    auto load_stage = [&](int s, int k0) {
#pragma unroll
        for (int i = 0; i < 3; i++) {
            int ch = tid + i * 256;
            int arr = ch >> 8;
            int r = (ch & 255) >> 1;
            int h8 = (ch & 1) * 8;
            const __half* g;
            if (arr == 0)      g = Ah + (size_t)(brow + r) * K + k0 + h8;
            else if (arr == 1) g = Al + (size_t)(brow + r) * K + k0 + h8;
            else               g = Bf + (size_t)(bcol + r) * K + k0 + h8;
            cpa16(smem_u32(&sm[s][arr][r][h8]), g);
        }
        asm volatile("cp.async.commit_group;");
    };

    const int NIT = K >> 4;
    load_stage(0, 0);
    for (int it = 0; it < NIT; ++it) {
        if (it + 1 < NIT) {
            load_stage((it + 1) & 1, (it + 1) * 16);
            asm volatile("cp.async.wait_group 1;");
        } else {
            asm volatile("cp.async.wait_group 0;");
        }
        __syncthreads();
        int s = it & 1;
        uint32_t ah[4][4], al[4][4];
#pragma unroll
        for (int mt = 0; mt < 4; mt++) {
            int row = wm * 64 + mt * 16 + (lane & 15);
            int col = (lane >> 4) * 8;
            ldsm4(ah[mt], &sm[s][0][row][col]);
            ldsm4(al[mt], &sm[s][1][row][col]);
        }
        uint32_t bf[4][2];
#pragma unroll
        for (int p = 0; p < 2; p++) {
            int row = wn * 32 + p * 16 + (lane & 15);
            int col = (lane >> 4) * 8;
            uint32_t t[4];
            ldsm4(t, &sm[s][2][row][col]);
            bf[2 * p][0] = t[0]; bf[2 * p][1] = t[2];
            bf[2 * p + 1][0] = t[1]; bf[2 * p + 1][1] = t[3];
        }
#pragma unroll
        for (int mt = 0; mt < 4; mt++)
#pragma unroll
            for (int nt = 0; nt < 4; nt++) {
                mma_f16(c[mt][nt], ah[mt], bf[nt]);
                mma_f16(c[mt][nt], al[mt], bf[nt]);
            }
        __syncthreads();
    }

    // Epilogue with bias (simple f32 stores — keeps regs under the 2-CTA cliff)
#pragma unroll
    for (int mt = 0; mt < 4; mt++) {
        int r0 = brow + wm * 64 + mt * 16 + (lane >> 2);
#pragma unroll
        for (int nt = 0; nt < 4; nt++) {
            int col = bcol + wn * 32 + nt * 8 + 2 * (lane & 3);
            float b0 = bias[col], b1 = bias[col + 1];
            float2 v0 = {c[mt][nt][0] + b0, c[mt][nt][1] + b1};
            float2 v1 = {c[mt][nt][2] + b0, c[mt][nt][3] + b1};
            *(float2*)(C + (size_t)r0 * N + col) = v0;
            *(float2*)(C + (size_t)(r0 + 8) * N + col) = v1;
        }
    }
}

// ---------------------------------------------------------------------------
// 4) Repack qkv fp32 -> per-head Q(scaled)/K fp16, V^T fp16 single
// ---------------------------------------------------------------------------
__global__ __launch_bounds__(256)
void repack_kernel(const float* __restrict__ qkv,
                   __half* __restrict__ Qf, __half* __restrict__ Kf,
                   __half* __restrict__ Vt) {
    __shared__ float vt[64][65];
    const int bh = blockIdx.y;
    const int b = bh >> 4, h = bh & 15;
    const int nb = blockIdx.x * 64;
    const float qscale = 0.125f * 1.4426950408889634f;  // scale * log2(e)

    for (int idx = threadIdx.x; idx < 64 * 192; idx += 256) {
        int r = idx / 192, cc = idx % 192;
        float v = qkv[(size_t)(b * N_ + nb + r) * QKV_N + h * 192 + cc];
        if (cc < 64) {
            Qf[((size_t)bh * N_ + nb + r) * 64 + cc] = __float2half_rn(v * qscale);
        } else if (cc < 128) {
            Kf[((size_t)bh * N_ + nb + r) * 64 + (cc - 64)] = __float2half_rn(v);
        } else {
            vt[cc - 128][r] = v;
        }
    }
    __syncthreads();
    for (int idx = threadIdx.x; idx < 64 * 64; idx += 256) {
        int d = idx >> 6, nl = idx & 63;
        Vt[((size_t)bh * 64 + d) * N_ + nb + nl] = __float2half_rn(vt[d][nl]);
    }
}

// ---------------------------------------------------------------------------
// 5) FA2 attention (EXACT R9): single fp16 QK, 2-term PV (P hi/lo x V).
//    Only epilogue changed: writes fp16 hi/lo (for 2-term out-projection).
// ---------------------------------------------------------------------------
__global__ __launch_bounds__(256)
void attn_kernel(const __half* __restrict__ Qf, const __half* __restrict__ Kf,
                 const __half* __restrict__ Vt,
                 __half* __restrict__ Oh, __half* __restrict__ Ol) {
    __shared__ __half ks[64][72];       // K tile [key][d]
    __shared__ __half vs[64][72];       // V tile, transposed [d][key]
    const int tid = threadIdx.x, lane = tid & 31, w = tid >> 5;
    const int bh = blockIdx.y, qb = blockIdx.x;
    const size_t qkbase = (size_t)bh * N_ * 64;
    const size_t vbase = (size_t)bh * 64 * N_;

    // Q fragments (fp16, pre-scaled) held in registers
    uint32_t qh[4][4];
    {
        int r0 = qb * 128 + w * 16 + (lane >> 2);
        int c0 = 2 * (lane & 3);
#pragma unroll
        for (int kd = 0; kd < 4; kd++) {
            const __half* ph = Qf + qkbase + (size_t)r0 * 64 + kd * 16 + c0;
            qh[kd][0] = *(const uint32_t*)(ph);
            qh[kd][1] = *(const uint32_t*)(ph + 8 * 64);
            qh[kd][2] = *(const uint32_t*)(ph + 8);
            qh[kd][3] = *(const uint32_t*)(ph + 8 * 64 + 8);
        }
    }

    float m0 = -1e30f, m1 = -1e30f, l0 = 0.f, l1 = 0.f;
    float o[8][4] = {};

    for (int kt0 = 0; kt0 < N_; kt0 += 64) {
        __syncthreads();
        // Load K (512 float4) + V (512) = 1024 chunks, 4/thread
#pragma unroll
        for (int i = 0; i < 4; i++) {
            int ch = tid + i * 256;
            int arr = ch >> 9;
            int rem = ch & 511;
            int r = rem >> 3;
            int h8 = (rem & 7) * 8;
            if (arr == 0)
                *(float4*)&ks[r][h8] = *(const float4*)(Kf + qkbase + (size_t)(kt0 + r) * 64 + h8);
            else
                *(float4*)&vs[r][h8] = *(const float4*)(Vt + vbase + (size_t)r * N_ + kt0 + h8);
        }
        __syncthreads();

        // S = Q K^T (single fp16 term, pre-scaled log2 domain)
        float sc[8][4] = {};
#pragma unroll
        for (int kd = 0; kd < 4; kd++) {
            const int colb = kd * 16 + (lane >> 4) * 8;
            uint32_t kb[8][2];
#pragma unroll
            for (int p = 0; p < 4; p++) {
                int row = p * 16 + (lane & 15);
                uint32_t tt[4];
                ldsm4(tt, &ks[row][colb]);
                kb[2 * p][0] = tt[0]; kb[2 * p][1] = tt[2];
                kb[2 * p + 1][0] = tt[1]; kb[2 * p + 1][1] = tt[3];
            }
#pragma unroll
            for (int nt = 0; nt < 8; nt++)
                mma_f16(sc[nt], qh[kd], kb[nt]);
        }

        // Online softmax (base-2)
        float mx0 = -1e30f, mx1 = -1e30f;
#pragma unroll
        for (int nt = 0; nt < 8; nt++) {
            mx0 = fmaxf(mx0, fmaxf(sc[nt][0], sc[nt][1]));
            mx1 = fmaxf(mx1, fmaxf(sc[nt][2], sc[nt][3]));
        }
        mx0 = fmaxf(mx0, __shfl_xor_sync(0xffffffffu, mx0, 1));
        mx0 = fmaxf(mx0, __shfl_xor_sync(0xffffffffu, mx0, 2));
        mx1 = fmaxf(mx1, __shfl_xor_sync(0xffffffffu, mx1, 1));
        mx1 = fmaxf(mx1, __shfl_xor_sync(0xffffffffu, mx1, 2));
        float mn0 = fmaxf(m0, mx0), mn1 = fmaxf(m1, mx1);
        float a0 = ex2f(m0 - mn0), a1 = ex2f(m1 - mn1);
        m0 = mn0; m1 = mn1;

        float sum0 = 0.f, sum1 = 0.f;
#pragma unroll
        for (int nt = 0; nt < 8; nt++) {
            sc[nt][0] = ex2f(sc[nt][0] - mn0);
            sc[nt][1] = ex2f(sc[nt][1] - mn0);
            sc[nt][2] = ex2f(sc[nt][2] - mn1);
            sc[nt][3] = ex2f(sc[nt][3] - mn1);
            sum0 += sc[nt][0] + sc[nt][1];
            sum1 += sc[nt][2] + sc[nt][3];
        }
        sum0 += __shfl_xor_sync(0xffffffffu, sum0, 1);
        sum0 += __shfl_xor_sync(0xffffffffu, sum0, 2);
        sum1 += __shfl_xor_sync(0xffffffffu, sum1, 1);
        sum1 += __shfl_xor_sync(0xffffffffu, sum1, 2);
        l0 = l0 * a0 + sum0;
        l1 = l1 * a1 + sum1;
#pragma unroll
        for (int nd = 0; nd < 8; nd++) {
            o[nd][0] *= a0; o[nd][1] *= a0;
            o[nd][2] *= a1; o[nd][3] *= a1;
        }

        // P fragments, fp16 hi/lo (exact P up to fp16 pair)
        uint32_t pah[4][4], pal[4][4];
#pragma unroll
        for (int kt = 0; kt < 4; kt++) {
            split2h(sc[2 * kt][0], sc[2 * kt][1], pah[kt][0], pal[kt][0]);
            split2h(sc[2 * kt][2], sc[2 * kt][3], pah[kt][1], pal[kt][1]);
            split2h(sc[2 * kt + 1][0], sc[2 * kt + 1][1], pah[kt][2], pal[kt][2]);
            split2h(sc[2 * kt + 1][2], sc[2 * kt + 1][3], pah[kt][3], pal[kt][3]);
        }

        // O += P V (2-term: (Ph+Pl) x V)
#pragma unroll
        for (int kt = 0; kt < 4; kt++) {
            const int colb = kt * 16 + (lane >> 4) * 8;
            uint32_t vb[8][2];
#pragma unroll
            for (int p = 0; p < 4; p++) {
                int row = p * 16 + (lane & 15);
                uint32_t tt[4];
                ldsm4(tt, &vs[row][colb]);
                vb[2 * p][0] = tt[0]; vb[2 * p][1] = tt[2];
                vb[2 * p + 1][0] = tt[1]; vb[2 * p + 1][1] = tt[3];
            }
#pragma unroll
            for (int nd = 0; nd < 8; nd++) {
                mma_f16(o[nd], pah[kt], vb[nd]);
                mma_f16(o[nd], pal[kt], vb[nd]);
            }
        }
    }

    // Epilogue: normalize, split to fp16 hi/lo for 2-term out-projection
    float i0 = 1.f / l0, i1 = 1.f / l1;
    int b = bh >> 4, h = bh & 15;
    int r0 = b * N_ + qb * 128 + w * 16 + (lane >> 2);
#pragma unroll
    for (int nd = 0; nd < 8; nd++) {
        int col = h * 64 + nd * 8 + 2 * (lane & 3);
        uint32_t hi, lo;
        split2h(o[nd][0] * i0, o[nd][1] * i0, hi, lo);
        *(uint32_t*)(Oh + (size_t)r0 * E_ + col) = hi;
        *(uint32_t*)(Ol + (size_t)r0 * E_ + col) = lo;
        split2h(o[nd][2] * i1, o[nd][3] * i1, hi, lo);
        *(uint32_t*)(Oh + (size_t)(r0 + 8) * E_ + col) = hi;
        *(uint32_t*)(Ol + (size_t)(r0 + 8) * E_ + col) = lo;
    }
}

// ---------------------------------------------------------------------------
extern "C" void kernel_launch(void* const* d_in, const int* in_sizes, int n_in,
                              void* d_out, int out_size) {
    (void)in_sizes; (void)n_in; (void)out_size;
    const float* x     = (const float*)d_in[0];
    const float* W_qkv = (const float*)d_in[1];
    const float* b_qkv = (const float*)d_in[2];
    const float* W_out = (const float*)d_in[3];
    const float* b_out = (const float*)d_in[4];
    float* out = (float*)d_out;

    __half *wq, *wo, *xh, *xl, *q_f, *k_f, *v_t, *o_h, *o_l;
    float* qkv;
    cudaGetSymbolAddress((void**)&wq, g_wqkv);
    cudaGetSymbolAddress((void**)&wo, g_wout);
    cudaGetSymbolAddress((void**)&xh, g_xh);
    cudaGetSymbolAddress((void**)&xl, g_xl);
    cudaGetSymbolAddress((void**)&qkv, g_qkv);
    cudaGetSymbolAddress((void**)&q_f, g_qf);
    cudaGetSymbolAddress((void**)&k_f, g_kf);
    cudaGetSymbolAddress((void**)&v_t, g_vt);
    cudaGetSymbolAddress((void**)&o_h, g_oh);
    cudaGetSymbolAddress((void**)&o_l, g_ol);

    // Prep: split x (fp16 hi/lo), transpose both weights to fp16
    split_x_kernel<<<(M_TOT * E_ / 4 + 255) / 256, 256>>>((const float4*)x, xh, xl,
                                                          M_TOT * E_ / 4);
    transpose_f16_kernel<<<dim3(QKV_N / 32, E_ / 32), 256>>>(W_qkv, wq, E_, QKV_N);
    transpose_f16_kernel<<<dim3(E_ / 32, E_ / 32), 256>>>(W_out, wo, E_, E_);

    // QKV projection (2-term fp16, f32 out)
    gemm_2t_kernel<<<dim3(QKV_N / 128, M_TOT / 128), 256>>>(
        xh, xl, wq, b_qkv, qkv, M_TOT, QKV_N, E_);

    // Repack into per-head fp16 layouts
    repack_kernel<<<dim3(N_ / 64, BH_), 256>>>(qkv, q_f, k_f, v_t);

    // Attention
    attn_kernel<<<dim3(N_ / 128, BH_), 256>>>(q_f, k_f, v_t, o_h, o_l);

    // Output projection (2-term fp16)
    gemm_2t_kernel<<<dim3(E_ / 128, M_TOT / 128), 256>>>(
        o_h, o_l, wo, b_out, out, M_TOT, E_, E_);
}

// round 13
// speedup vs baseline: 2.0666x; 1.3646x over previous
#include <cuda_runtime.h>
#include <cuda_bf16.h>
#include <cuda_fp16.h>
#include <stdint.h>

// Problem constants
#define B_   2
#define N_   2048
#define E_   1024
#define H_   16
#define HD_  64
#define M_TOT  (B_ * N_)     // 4096
#define QKV_N  (3 * E_)      // 3072
#define BH_    (B_ * H_)     // 32

// ---------------------------------------------------------------------------
// Device scratch (allocation-free rule)
// ---------------------------------------------------------------------------
__device__ __half g_wqkv[(size_t)QKV_N * E_];   // W_qkv^T fp16
__device__ __half g_wout[(size_t)E_ * E_];      // W_out^T fp16
__device__ __half g_xf[(size_t)M_TOT * E_];     // x fp16 single
__device__ float g_qkv[(size_t)M_TOT * QKV_N];
__device__ __half g_qf[(size_t)BH_ * N_ * HD_];
__device__ __half g_kf[(size_t)BH_ * N_ * HD_];
__device__ __half g_vt[(size_t)BH_ * HD_ * N_];
__device__ __half g_oh[(size_t)M_TOT * E_];     // attn out hi fp16
__device__ __half g_ol[(size_t)M_TOT * E_];     // attn out lo fp16

// ---------------------------------------------------------------------------
// Helpers
// ---------------------------------------------------------------------------
__device__ __forceinline__ uint32_t smem_u32(const void* p) {
    uint32_t a;
    asm("{ .reg .u64 t; cvta.to.shared.u64 t, %1; cvt.u32.u64 %0, t; }"
        : "=r"(a) : "l"(p));
    return a;
}

__device__ __forceinline__ void mma_f16(float c[4], const uint32_t a[4],
                                        const uint32_t b[2]) {
    asm volatile(
        "mma.sync.aligned.m16n8k16.row.col.f32.f16.f16.f32 "
        "{%0,%1,%2,%3},{%4,%5,%6,%7},{%8,%9},{%0,%1,%2,%3};"
        : "+f"(c[0]), "+f"(c[1]), "+f"(c[2]), "+f"(c[3])
        : "r"(a[0]), "r"(a[1]), "r"(a[2]), "r"(a[3]), "r"(b[0]), "r"(b[1]));
}

__device__ __forceinline__ void ldsm4(uint32_t r[4], const void* p) {
    uint32_t a = smem_u32(p);
    asm volatile("ldmatrix.sync.aligned.m8n8.x4.shared.b16 {%0,%1,%2,%3},[%4];"
                 : "=r"(r[0]), "=r"(r[1]), "=r"(r[2]), "=r"(r[3])
                 : "r"(a));
}

__device__ __forceinline__ void cpa16(uint32_t s, const void* g) {
    asm volatile("cp.async.cg.shared.global [%0],[%1],16;" ::"r"(s), "l"(g));
}

__device__ __forceinline__ float ex2f(float x) {
    float r;
    asm("ex2.approx.ftz.f32 %0,%1;" : "=f"(r) : "f"(x));
    return r;
}

// Pack two floats to fp16x2
__device__ __forceinline__ uint32_t pack2h(float x, float y) {
    __half2 t = __floats2half2_rn(x, y);
    return *reinterpret_cast<uint32_t*>(&t);
}

// Split two floats into packed fp16 hi/lo pairs
__device__ __forceinline__ void split2h(float x, float y, uint32_t& hi, uint32_t& lo) {
    __half xh = __float2half_rn(x);
    __half yh = __float2half_rn(y);
    float xr = x - __half2float(xh);
    float yr = y - __half2float(yh);
    __half2 h2, l2;
    h2.x = xh; h2.y = yh;
    l2.x = __float2half_rn(xr); l2.y = __float2half_rn(yr);
    hi = *reinterpret_cast<uint32_t*>(&h2);
    lo = *reinterpret_cast<uint32_t*>(&l2);
}

// ---------------------------------------------------------------------------
// 1) Elementwise cast of x -> fp16 single
// ---------------------------------------------------------------------------
__global__ void cast_x_kernel(const float4* __restrict__ X,
                              __half* __restrict__ Xf, int n4) {
    int i = blockIdx.x * blockDim.x + threadIdx.x;
    if (i >= n4) return;
    float4 v = X[i];
    *(uint32_t*)(Xf + (size_t)i * 4)     = pack2h(v.x, v.y);
    *(uint32_t*)(Xf + (size_t)i * 4 + 2) = pack2h(v.z, v.w);
}

// ---------------------------------------------------------------------------
// 2) Transpose W[K,N] -> Wt fp16 single [N,K]
// ---------------------------------------------------------------------------
__global__ void transpose_f16_kernel(const float* __restrict__ W,
                                     __half* __restrict__ T, int K, int N) {
    __shared__ float t[32][33];
    int k0 = blockIdx.y * 32, n0 = blockIdx.x * 32;
    int tx = threadIdx.x & 31, ty = threadIdx.x >> 5;
#pragma unroll
    for (int i = 0; i < 4; i++)
        t[ty + 8 * i][tx] = W[(size_t)(k0 + ty + 8 * i) * N + n0 + tx];
    __syncthreads();
#pragma unroll
    for (int i = 0; i < 4; i++)
        T[(size_t)(n0 + ty + 8 * i) * K + k0 + tx] = __float2half_rn(t[tx][ty + 8 * i]);
}

// ---------------------------------------------------------------------------
// 3a) Single-term fp16 GEMM, f32 output: C = A@B^T + bias (QKV projection)
//     Same R2/R9 pipeline skeleton: BK=16, 2-stage cp.async, 2 smem arrays.
// ---------------------------------------------------------------------------
__global__ __launch_bounds__(256)
void gemm_1t_kernel(const __half* __restrict__ Af, const __half* __restrict__ Bf,
                    const float* __restrict__ bias,
                    float* __restrict__ C, int M, int N, int K) {
    __shared__ __half sm[2][2][128][24];  // 24KB; arr: A, B
    const int tid = threadIdx.x, lane = tid & 31, w = tid >> 5;
    const int wm = w >> 2, wn = w & 3;    // 2 x 4 warp grid
    const int brow = blockIdx.y * 128, bcol = blockIdx.x * 128;

    float c[4][4][4] = {};

    auto load_stage = [&](int s, int k0) {
#pragma unroll
        for (int i = 0; i < 2; i++) {
            int ch = tid + i * 256;   // 0..511
            int arr = ch >> 8;
            int r = (ch & 255) >> 1;
            int h8 = (ch & 1) * 8;
            const __half* g;
            if (arr == 0) g = Af + (size_t)(brow + r) * K + k0 + h8;
            else          g = Bf + (size_t)(bcol + r) * K + k0 + h8;
            cpa16(smem_u32(&sm[s][arr][r][h8]), g);
        }
        asm volatile("cp.async.commit_group;");
    };

    const int NIT = K >> 4;
    load_stage(0, 0);
    for (int it = 0; it < NIT; ++it) {
        if (it + 1 < NIT) {
            load_stage((it + 1) & 1, (it + 1) * 16);
            asm volatile("cp.async.wait_group 1;");
        } else {
            asm volatile("cp.async.wait_group 0;");
        }
        __syncthreads();
        int s = it & 1;
        uint32_t af[4][4];
#pragma unroll
        for (int mt = 0; mt < 4; mt++) {
            int row = wm * 64 + mt * 16 + (lane & 15);
            int col = (lane >> 4) * 8;
            ldsm4(af[mt], &sm[s][0][row][col]);
        }
        uint32_t bf[4][2];
#pragma unroll
        for (int p = 0; p < 2; p++) {
            int row = wn * 32 + p * 16 + (lane & 15);
            int col = (lane >> 4) * 8;
            uint32_t t[4];
            ldsm4(t, &sm[s][1][row][col]);
            bf[2 * p][0] = t[0]; bf[2 * p][1] = t[2];
            bf[2 * p + 1][0] = t[1]; bf[2 * p + 1][1] = t[3];
        }
#pragma unroll
        for (int mt = 0; mt < 4; mt++)
#pragma unroll
            for (int nt = 0; nt < 4; nt++)
                mma_f16(c[mt][nt], af[mt], bf[nt]);
        __syncthreads();
    }

#pragma unroll
    for (int mt = 0; mt < 4; mt++) {
        int r0 = brow + wm * 64 + mt * 16 + (lane >> 2);
#pragma unroll
        for (int nt = 0; nt < 4; nt++) {
            int col = bcol + wn * 32 + nt * 8 + 2 * (lane & 3);
            float b0 = bias[col], b1 = bias[col + 1];
            float2 v0 = {c[mt][nt][0] + b0, c[mt][nt][1] + b1};
            float2 v1 = {c[mt][nt][2] + b0, c[mt][nt][3] + b1};
            *(float2*)(C + (size_t)r0 * N + col) = v0;
            *(float2*)(C + (size_t)(r0 + 8) * N + col) = v1;
        }
    }
}

// ---------------------------------------------------------------------------
// 3b) 2-term fp16 GEMM, f32 output (out-projection; R9/R11-proven)
// ---------------------------------------------------------------------------
__global__ __launch_bounds__(256)
void gemm_2t_kernel(const __half* __restrict__ Ah, const __half* __restrict__ Al,
                    const __half* __restrict__ Bf,
                    const float* __restrict__ bias,
                    float* __restrict__ C, int M, int N, int K) {
    __shared__ __half sm[2][3][128][24];  // 36KB; arr: Ah, Al, B
    const int tid = threadIdx.x, lane = tid & 31, w = tid >> 5;
    const int wm = w >> 2, wn = w & 3;
    const int brow = blockIdx.y * 128, bcol = blockIdx.x * 128;

    float c[4][4][4] = {};

    auto load_stage = [&](int s, int k0) {
#pragma unroll
        for (int i = 0; i < 3; i++) {
            int ch = tid + i * 256;
            int arr = ch >> 8;
            int r = (ch & 255) >> 1;
            int h8 = (ch & 1) * 8;
            const __half* g;
            if (arr == 0)      g = Ah + (size_t)(brow + r) * K + k0 + h8;
            else if (arr == 1) g = Al + (size_t)(brow + r) * K + k0 + h8;
            else               g = Bf + (size_t)(bcol + r) * K + k0 + h8;
            cpa16(smem_u32(&sm[s][arr][r][h8]), g);
        }
        asm volatile("cp.async.commit_group;");
    };

    const int NIT = K >> 4;
    load_stage(0, 0);
    for (int it = 0; it < NIT; ++it) {
        if (it + 1 < NIT) {
            load_stage((it + 1) & 1, (it + 1) * 16);
            asm volatile("cp.async.wait_group 1;");
        } else {
            asm volatile("cp.async.wait_group 0;");
        }
        __syncthreads();
        int s = it & 1;
        uint32_t ah[4][4], al[4][4];
#pragma unroll
        for (int mt = 0; mt < 4; mt++) {
            int row = wm * 64 + mt * 16 + (lane & 15);
            int col = (lane >> 4) * 8;
            ldsm4(ah[mt], &sm[s][0][row][col]);
            ldsm4(al[mt], &sm[s][1][row][col]);
        }
        uint32_t bf[4][2];
#pragma unroll
        for (int p = 0; p < 2; p++) {
            int row = wn * 32 + p * 16 + (lane & 15);
            int col = (lane >> 4) * 8;
            uint32_t t[4];
            ldsm4(t, &sm[s][2][row][col]);
            bf[2 * p][0] = t[0]; bf[2 * p][1] = t[2];
            bf[2 * p + 1][0] = t[1]; bf[2 * p + 1][1] = t[3];
        }
#pragma unroll
        for (int mt = 0; mt < 4; mt++)
#pragma unroll
            for (int nt = 0; nt < 4; nt++) {
                mma_f16(c[mt][nt], ah[mt], bf[nt]);
                mma_f16(c[mt][nt], al[mt], bf[nt]);
            }
        __syncthreads();
    }

#pragma unroll
    for (int mt = 0; mt < 4; mt++) {
        int r0 = brow + wm * 64 + mt * 16 + (lane >> 2);
#pragma unroll
        for (int nt = 0; nt < 4; nt++) {
            int col = bcol + wn * 32 + nt * 8 + 2 * (lane & 3);
            float b0 = bias[col], b1 = bias[col + 1];
            float2 v0 = {c[mt][nt][0] + b0, c[mt][nt][1] + b1};
            float2 v1 = {c[mt][nt][2] + b0, c[mt][nt][3] + b1};
            *(float2*)(C + (size_t)r0 * N + col) = v0;
            *(float2*)(C + (size_t)(r0 + 8) * N + col) = v1;
        }
    }
}

// ---------------------------------------------------------------------------
// 4) Repack qkv fp32 -> per-head Q(scaled)/K fp16, V^T fp16 single
// ---------------------------------------------------------------------------
__global__ __launch_bounds__(256)
void repack_kernel(const float* __restrict__ qkv,
                   __half* __restrict__ Qf, __half* __restrict__ Kf,
                   __half* __restrict__ Vt) {
    __shared__ float vt[64][65];
    const int bh = blockIdx.y;
    const int b = bh >> 4, h = bh & 15;
    const int nb = blockIdx.x * 64;
    const float qscale = 0.125f * 1.4426950408889634f;  // scale * log2(e)

    for (int idx = threadIdx.x; idx < 64 * 192; idx += 256) {
        int r = idx / 192, cc = idx % 192;
        float v = qkv[(size_t)(b * N_ + nb + r) * QKV_N + h * 192 + cc];
        if (cc < 64) {
            Qf[((size_t)bh * N_ + nb + r) * 64 + cc] = __float2half_rn(v * qscale);
        } else if (cc < 128) {
            Kf[((size_t)bh * N_ + nb + r) * 64 + (cc - 64)] = __float2half_rn(v);
        } else {
            vt[cc - 128][r] = v;
        }
    }
    __syncthreads();
    for (int idx = threadIdx.x; idx < 64 * 64; idx += 256) {
        int d = idx >> 6, nl = idx & 63;
        Vt[((size_t)bh * 64 + d) * N_ + nb + nl] = __float2half_rn(vt[d][nl]);
    }
}

// ---------------------------------------------------------------------------
// 5) FA2 attention: single fp16 QK, single-term PV (P fp16 x V fp16).
// ---------------------------------------------------------------------------
__global__ __launch_bounds__(256)
void attn_kernel(const __half* __restrict__ Qf, const __half* __restrict__ Kf,
                 const __half* __restrict__ Vt,
                 __half* __restrict__ Oh, __half* __restrict__ Ol) {
    __shared__ __half ks[64][72];       // K tile [key][d]
    __shared__ __half vs[64][72];       // V tile, transposed [d][key]
    const int tid = threadIdx.x, lane = tid & 31, w = tid >> 5;
    const int bh = blockIdx.y, qb = blockIdx.x;
    const size_t qkbase = (size_t)bh * N_ * 64;
    const size_t vbase = (size_t)bh * 64 * N_;

    // Q fragments (fp16, pre-scaled) held in registers
    uint32_t qh[4][4];
    {
        int r0 = qb * 128 + w * 16 + (lane >> 2);
        int c0 = 2 * (lane & 3);
#pragma unroll
        for (int kd = 0; kd < 4; kd++) {
            const __half* ph = Qf + qkbase + (size_t)r0 * 64 + kd * 16 + c0;
            qh[kd][0] = *(const uint32_t*)(ph);
            qh[kd][1] = *(const uint32_t*)(ph + 8 * 64);
            qh[kd][2] = *(const uint32_t*)(ph + 8);
            qh[kd][3] = *(const uint32_t*)(ph + 8 * 64 + 8);
        }
    }

    float m0 = -1e30f, m1 = -1e30f, l0 = 0.f, l1 = 0.f;
    float o[8][4] = {};

    for (int kt0 = 0; kt0 < N_; kt0 += 64) {
        __syncthreads();
        // Load K (512 float4) + V (512) = 1024 chunks, 4/thread
#pragma unroll
        for (int i = 0; i < 4; i++) {
            int ch = tid + i * 256;
            int arr = ch >> 9;
            int rem = ch & 511;
            int r = rem >> 3;
            int h8 = (rem & 7) * 8;
            if (arr == 0)
                *(float4*)&ks[r][h8] = *(const float4*)(Kf + qkbase + (size_t)(kt0 + r) * 64 + h8);
            else
                *(float4*)&vs[r][h8] = *(const float4*)(Vt + vbase + (size_t)r * N_ + kt0 + h8);
        }
        __syncthreads();

        // S = Q K^T (single fp16 term, pre-scaled log2 domain)
        float sc[8][4] = {};
#pragma unroll
        for (int kd = 0; kd < 4; kd++) {
            const int colb = kd * 16 + (lane >> 4) * 8;
            uint32_t kb[8][2];
#pragma unroll
            for (int p = 0; p < 4; p++) {
                int row = p * 16 + (lane & 15);
                uint32_t tt[4];
                ldsm4(tt, &ks[row][colb]);
                kb[2 * p][0] = tt[0]; kb[2 * p][1] = tt[2];
                kb[2 * p + 1][0] = tt[1]; kb[2 * p + 1][1] = tt[3];
            }
#pragma unroll
            for (int nt = 0; nt < 8; nt++)
                mma_f16(sc[nt], qh[kd], kb[nt]);
        }

        // Online softmax (base-2)
        float mx0 = -1e30f, mx1 = -1e30f;
#pragma unroll
        for (int nt = 0; nt < 8; nt++) {
            mx0 = fmaxf(mx0, fmaxf(sc[nt][0], sc[nt][1]));
            mx1 = fmaxf(mx1, fmaxf(sc[nt][2], sc[nt][3]));
        }
        mx0 = fmaxf(mx0, __shfl_xor_sync(0xffffffffu, mx0, 1));
        mx0 = fmaxf(mx0, __shfl_xor_sync(0xffffffffu, mx0, 2));
        mx1 = fmaxf(mx1, __shfl_xor_sync(0xffffffffu, mx1, 1));
        mx1 = fmaxf(mx1, __shfl_xor_sync(0xffffffffu, mx1, 2));
        float mn0 = fmaxf(m0, mx0), mn1 = fmaxf(m1, mx1);
        float a0 = ex2f(m0 - mn0), a1 = ex2f(m1 - mn1);
        m0 = mn0; m1 = mn1;

        float sum0 = 0.f, sum1 = 0.f;
#pragma unroll
        for (int nt = 0; nt < 8; nt++) {
            sc[nt][0] = ex2f(sc[nt][0] - mn0);
            sc[nt][1] = ex2f(sc[nt][1] - mn0);
            sc[nt][2] = ex2f(sc[nt][2] - mn1);
            sc[nt][3] = ex2f(sc[nt][3] - mn1);
            sum0 += sc[nt][0] + sc[nt][1];
            sum1 += sc[nt][2] + sc[nt][3];
        }
        sum0 += __shfl_xor_sync(0xffffffffu, sum0, 1);
        sum0 += __shfl_xor_sync(0xffffffffu, sum0, 2);
        sum1 += __shfl_xor_sync(0xffffffffu, sum1, 1);
        sum1 += __shfl_xor_sync(0xffffffffu, sum1, 2);
        l0 = l0 * a0 + sum0;
        l1 = l1 * a1 + sum1;
#pragma unroll
        for (int nd = 0; nd < 8; nd++) {
            o[nd][0] *= a0; o[nd][1] *= a0;
            o[nd][2] *= a1; o[nd][3] *= a1;
        }

        // P fragments, single fp16
        uint32_t pa[4][4];
#pragma unroll
        for (int kt = 0; kt < 4; kt++) {
            pa[kt][0] = pack2h(sc[2 * kt][0], sc[2 * kt][1]);
            pa[kt][1] = pack2h(sc[2 * kt][2], sc[2 * kt][3]);
            pa[kt][2] = pack2h(sc[2 * kt + 1][0], sc[2 * kt + 1][1]);
            pa[kt][3] = pack2h(sc[2 * kt + 1][2], sc[2 * kt + 1][3]);
        }

        // O += P V (single term)
#pragma unroll
        for (int kt = 0; kt < 4; kt++) {
            const int colb = kt * 16 + (lane >> 4) * 8;
            uint32_t vb[8][2];
#pragma unroll
            for (int p = 0; p < 4; p++) {
                int row = p * 16 + (lane & 15);
                uint32_t tt[4];
                ldsm4(tt, &vs[row][colb]);
                vb[2 * p][0] = tt[0]; vb[2 * p][1] = tt[2];
                vb[2 * p + 1][0] = tt[1]; vb[2 * p + 1][1] = tt[3];
            }
#pragma unroll
            for (int nd = 0; nd < 8; nd++)
                mma_f16(o[nd], pa[kt], vb[nd]);
        }
    }

    // Epilogue: normalize, split to fp16 hi/lo for 2-term out-projection
    float i0 = 1.f / l0, i1 = 1.f / l1;
    int b = bh >> 4, h = bh & 15;
    int r0 = b * N_ + qb * 128 + w * 16 + (lane >> 2);
#pragma unroll
    for (int nd = 0; nd < 8; nd++) {
        int col = h * 64 + nd * 8 + 2 * (lane & 3);
        uint32_t hi, lo;
        split2h(o[nd][0] * i0, o[nd][1] * i0, hi, lo);
        *(uint32_t*)(Oh + (size_t)r0 * E_ + col) = hi;
        *(uint32_t*)(Ol + (size_t)r0 * E_ + col) = lo;
        split2h(o[nd][2] * i1, o[nd][3] * i1, hi, lo);
        *(uint32_t*)(Oh + (size_t)(r0 + 8) * E_ + col) = hi;
        *(uint32_t*)(Ol + (size_t)(r0 + 8) * E_ + col) = lo;
    }
}

// ---------------------------------------------------------------------------
extern "C" void kernel_launch(void* const* d_in, const int* in_sizes, int n_in,
                              void* d_out, int out_size) {
    (void)in_sizes; (void)n_in; (void)out_size;
    const float* x     = (const float*)d_in[0];
    const float* W_qkv = (const float*)d_in[1];
    const float* b_qkv = (const float*)d_in[2];
    const float* W_out = (const float*)d_in[3];
    const float* b_out = (const float*)d_in[4];
    float* out = (float*)d_out;

    __half *wq, *wo, *xf, *q_f, *k_f, *v_t, *o_h, *o_l;
    float* qkv;
    cudaGetSymbolAddress((void**)&wq, g_wqkv);
    cudaGetSymbolAddress((void**)&wo, g_wout);
    cudaGetSymbolAddress((void**)&xf, g_xf);
    cudaGetSymbolAddress((void**)&qkv, g_qkv);
    cudaGetSymbolAddress((void**)&q_f, g_qf);
    cudaGetSymbolAddress((void**)&k_f, g_kf);
    cudaGetSymbolAddress((void**)&v_t, g_vt);
    cudaGetSymbolAddress((void**)&o_h, g_oh);
    cudaGetSymbolAddress((void**)&o_l, g_ol);

    // Prep: cast x to fp16, transpose both weights to fp16
    cast_x_kernel<<<(M_TOT * E_ / 4 + 255) / 256, 256>>>((const float4*)x, xf,
                                                         M_TOT * E_ / 4);
    transpose_f16_kernel<<<dim3(QKV_N / 32, E_ / 32), 256>>>(W_qkv, wq, E_, QKV_N);
    transpose_f16_kernel<<<dim3(E_ / 32, E_ / 32), 256>>>(W_out, wo, E_, E_);

    // QKV projection (single-term fp16, f32 out)
    gemm_1t_kernel<<<dim3(QKV_N / 128, M_TOT / 128), 256>>>(
        xf, wq, b_qkv, qkv, M_TOT, QKV_N, E_);

    // Repack into per-head fp16 layouts
    repack_kernel<<<dim3(N_ / 64, BH_), 256>>>(qkv, q_f, k_f, v_t);

    // Attention (single-term QK, single-term PV)
    attn_kernel<<<dim3(N_ / 128, BH_), 256>>>(q_f, k_f, v_t, o_h, o_l);

    // Output projection (2-term fp16)
    gemm_2t_kernel<<<dim3(E_ / 128, M_TOT / 128), 256>>>(
        o_h, o_l, wo, b_out, out, M_TOT, E_, E_);
}

// round 14
// speedup vs baseline: 2.2457x; 1.0867x over previous
#include <cuda_runtime.h>
#include <cuda_bf16.h>
#include <cuda_fp16.h>
#include <stdint.h>

// Problem constants
#define B_   2
#define N_   2048
#define E_   1024
#define H_   16
#define HD_  64
#define M_TOT  (B_ * N_)     // 4096
#define QKV_N  (3 * E_)      // 3072
#define BH_    (B_ * H_)     // 32

// ---------------------------------------------------------------------------
// Device scratch (allocation-free rule)
// ---------------------------------------------------------------------------
__device__ __half g_wqkv[(size_t)QKV_N * E_];   // W_qkv^T fp16
__device__ __half g_wout[(size_t)E_ * E_];      // W_out^T fp16
__device__ __half g_xf[(size_t)M_TOT * E_];     // x fp16 single
__device__ float g_qkv[(size_t)M_TOT * QKV_N];
__device__ __half g_qf[(size_t)BH_ * N_ * HD_];
__device__ __half g_kf[(size_t)BH_ * N_ * HD_];
__device__ __half g_vt[(size_t)BH_ * HD_ * N_];
__device__ __half g_of[(size_t)M_TOT * E_];     // attn out fp16 single

// ---------------------------------------------------------------------------
// Helpers
// ---------------------------------------------------------------------------
__device__ __forceinline__ uint32_t smem_u32(const void* p) {
    uint32_t a;
    asm("{ .reg .u64 t; cvta.to.shared.u64 t, %1; cvt.u32.u64 %0, t; }"
        : "=r"(a) : "l"(p));
    return a;
}

__device__ __forceinline__ void mma_f16(float c[4], const uint32_t a[4],
                                        const uint32_t b[2]) {
    asm volatile(
        "mma.sync.aligned.m16n8k16.row.col.f32.f16.f16.f32 "
        "{%0,%1,%2,%3},{%4,%5,%6,%7},{%8,%9},{%0,%1,%2,%3};"
        : "+f"(c[0]), "+f"(c[1]), "+f"(c[2]), "+f"(c[3])
        : "r"(a[0]), "r"(a[1]), "r"(a[2]), "r"(a[3]), "r"(b[0]), "r"(b[1]));
}

__device__ __forceinline__ void ldsm4(uint32_t r[4], const void* p) {
    uint32_t a = smem_u32(p);
    asm volatile("ldmatrix.sync.aligned.m8n8.x4.shared.b16 {%0,%1,%2,%3},[%4];"
                 : "=r"(r[0]), "=r"(r[1]), "=r"(r[2]), "=r"(r[3])
                 : "r"(a));
}

__device__ __forceinline__ void cpa16(uint32_t s, const void* g) {
    asm volatile("cp.async.cg.shared.global [%0],[%1],16;" ::"r"(s), "l"(g));
}

__device__ __forceinline__ float ex2f(float x) {
    float r;
    asm("ex2.approx.ftz.f32 %0,%1;" : "=f"(r) : "f"(x));
    return r;
}

// Pack two floats to fp16x2
__device__ __forceinline__ uint32_t pack2h(float x, float y) {
    __half2 t = __floats2half2_rn(x, y);
    return *reinterpret_cast<uint32_t*>(&t);
}

// ---------------------------------------------------------------------------
// 1) Elementwise cast of x -> fp16 single
// ---------------------------------------------------------------------------
__global__ void cast_x_kernel(const float4* __restrict__ X,
                              __half* __restrict__ Xf, int n4) {
    int i = blockIdx.x * blockDim.x + threadIdx.x;
    if (i >= n4) return;
    float4 v = X[i];
    *(uint32_t*)(Xf + (size_t)i * 4)     = pack2h(v.x, v.y);
    *(uint32_t*)(Xf + (size_t)i * 4 + 2) = pack2h(v.z, v.w);
}

// ---------------------------------------------------------------------------
// 2) Transpose W[K,N] -> Wt fp16 single [N,K]
// ---------------------------------------------------------------------------
__global__ void transpose_f16_kernel(const float* __restrict__ W,
                                     __half* __restrict__ T, int K, int N) {
    __shared__ float t[32][33];
    int k0 = blockIdx.y * 32, n0 = blockIdx.x * 32;
    int tx = threadIdx.x & 31, ty = threadIdx.x >> 5;
#pragma unroll
    for (int i = 0; i < 4; i++)
        t[ty + 8 * i][tx] = W[(size_t)(k0 + ty + 8 * i) * N + n0 + tx];
    __syncthreads();
#pragma unroll
    for (int i = 0; i < 4; i++)
        T[(size_t)(n0 + ty + 8 * i) * K + k0 + tx] = __float2half_rn(t[tx][ty + 8 * i]);
}

// ---------------------------------------------------------------------------
// 3) Single-term fp16 GEMM, f32 output: C = A@B^T + bias
//    (used for BOTH projections; R13-proven)
// ---------------------------------------------------------------------------
__global__ __launch_bounds__(256)
void gemm_1t_kernel(const __half* __restrict__ Af, const __half* __restrict__ Bf,
                    const float* __restrict__ bias,
                    float* __restrict__ C, int M, int N, int K) {
    __shared__ __half sm[2][2][128][24];  // 24KB; arr: A, B
    const int tid = threadIdx.x, lane = tid & 31, w = tid >> 5;
    const int wm = w >> 2, wn = w & 3;    // 2 x 4 warp grid
    const int brow = blockIdx.y * 128, bcol = blockIdx.x * 128;

    float c[4][4][4] = {};

    auto load_stage = [&](int s, int k0) {
#pragma unroll
        for (int i = 0; i < 2; i++) {
            int ch = tid + i * 256;   // 0..511
            int arr = ch >> 8;
            int r = (ch & 255) >> 1;
            int h8 = (ch & 1) * 8;
            const __half* g;
            if (arr == 0) g = Af + (size_t)(brow + r) * K + k0 + h8;
            else          g = Bf + (size_t)(bcol + r) * K + k0 + h8;
            cpa16(smem_u32(&sm[s][arr][r][h8]), g);
        }
        asm volatile("cp.async.commit_group;");
    };

    const int NIT = K >> 4;
    load_stage(0, 0);
    for (int it = 0; it < NIT; ++it) {
        if (it + 1 < NIT) {
            load_stage((it + 1) & 1, (it + 1) * 16);
            asm volatile("cp.async.wait_group 1;");
        } else {
            asm volatile("cp.async.wait_group 0;");
        }
        __syncthreads();
        int s = it & 1;
        uint32_t af[4][4];
#pragma unroll
        for (int mt = 0; mt < 4; mt++) {
            int row = wm * 64 + mt * 16 + (lane & 15);
            int col = (lane >> 4) * 8;
            ldsm4(af[mt], &sm[s][0][row][col]);
        }
        uint32_t bf[4][2];
#pragma unroll
        for (int p = 0; p < 2; p++) {
            int row = wn * 32 + p * 16 + (lane & 15);
            int col = (lane >> 4) * 8;
            uint32_t t[4];
            ldsm4(t, &sm[s][1][row][col]);
            bf[2 * p][0] = t[0]; bf[2 * p][1] = t[2];
            bf[2 * p + 1][0] = t[1]; bf[2 * p + 1][1] = t[3];
        }
#pragma unroll
        for (int mt = 0; mt < 4; mt++)
#pragma unroll
            for (int nt = 0; nt < 4; nt++)
                mma_f16(c[mt][nt], af[mt], bf[nt]);
        __syncthreads();
    }

#pragma unroll
    for (int mt = 0; mt < 4; mt++) {
        int r0 = brow + wm * 64 + mt * 16 + (lane >> 2);
#pragma unroll
        for (int nt = 0; nt < 4; nt++) {
            int col = bcol + wn * 32 + nt * 8 + 2 * (lane & 3);
            float b0 = bias[col], b1 = bias[col + 1];
            float2 v0 = {c[mt][nt][0] + b0, c[mt][nt][1] + b1};
            float2 v1 = {c[mt][nt][2] + b0, c[mt][nt][3] + b1};
            *(float2*)(C + (size_t)r0 * N + col) = v0;
            *(float2*)(C + (size_t)(r0 + 8) * N + col) = v1;
        }
    }
}

// ---------------------------------------------------------------------------
// 4) Repack qkv fp32 -> per-head Q(scaled)/K fp16, V^T fp16 single
// ---------------------------------------------------------------------------
__global__ __launch_bounds__(256)
void repack_kernel(const float* __restrict__ qkv,
                   __half* __restrict__ Qf, __half* __restrict__ Kf,
                   __half* __restrict__ Vt) {
    __shared__ float vt[64][65];
    const int bh = blockIdx.y;
    const int b = bh >> 4, h = bh & 15;
    const int nb = blockIdx.x * 64;
    const float qscale = 0.125f * 1.4426950408889634f;  // scale * log2(e)

    for (int idx = threadIdx.x; idx < 64 * 192; idx += 256) {
        int r = idx / 192, cc = idx % 192;
        float v = qkv[(size_t)(b * N_ + nb + r) * QKV_N + h * 192 + cc];
        if (cc < 64) {
            Qf[((size_t)bh * N_ + nb + r) * 64 + cc] = __float2half_rn(v * qscale);
        } else if (cc < 128) {
            Kf[((size_t)bh * N_ + nb + r) * 64 + (cc - 64)] = __float2half_rn(v);
        } else {
            vt[cc - 128][r] = v;
        }
    }
    __syncthreads();
    for (int idx = threadIdx.x; idx < 64 * 64; idx += 256) {
        int d = idx >> 6, nl = idx & 63;
        Vt[((size_t)bh * 64 + d) * N_ + nb + nl] = __float2half_rn(vt[d][nl]);
    }
}

// ---------------------------------------------------------------------------
// 5) FA2 attention: single fp16 QK, single-term PV. fp16-single output.
// ---------------------------------------------------------------------------
__global__ __launch_bounds__(256)
void attn_kernel(const __half* __restrict__ Qf, const __half* __restrict__ Kf,
                 const __half* __restrict__ Vt,
                 __half* __restrict__ Of) {
    __shared__ __half ks[64][72];       // K tile [key][d]
    __shared__ __half vs[64][72];       // V tile, transposed [d][key]
    const int tid = threadIdx.x, lane = tid & 31, w = tid >> 5;
    const int bh = blockIdx.y, qb = blockIdx.x;
    const size_t qkbase = (size_t)bh * N_ * 64;
    const size_t vbase = (size_t)bh * 64 * N_;

    // Q fragments (fp16, pre-scaled) held in registers
    uint32_t qh[4][4];
    {
        int r0 = qb * 128 + w * 16 + (lane >> 2);
        int c0 = 2 * (lane & 3);
#pragma unroll
        for (int kd = 0; kd < 4; kd++) {
            const __half* ph = Qf + qkbase + (size_t)r0 * 64 + kd * 16 + c0;
            qh[kd][0] = *(const uint32_t*)(ph);
            qh[kd][1] = *(const uint32_t*)(ph + 8 * 64);
            qh[kd][2] = *(const uint32_t*)(ph + 8);
            qh[kd][3] = *(const uint32_t*)(ph + 8 * 64 + 8);
        }
    }

    float m0 = -1e30f, m1 = -1e30f, l0 = 0.f, l1 = 0.f;
    float o[8][4] = {};

    for (int kt0 = 0; kt0 < N_; kt0 += 64) {
        __syncthreads();
        // Load K (512 float4) + V (512) = 1024 chunks, 4/thread
#pragma unroll
        for (int i = 0; i < 4; i++) {
            int ch = tid + i * 256;
            int arr = ch >> 9;
            int rem = ch & 511;
            int r = rem >> 3;
            int h8 = (rem & 7) * 8;
            if (arr == 0)
                *(float4*)&ks[r][h8] = *(const float4*)(Kf + qkbase + (size_t)(kt0 + r) * 64 + h8);
            else
                *(float4*)&vs[r][h8] = *(const float4*)(Vt + vbase + (size_t)r * N_ + kt0 + h8);
        }
        __syncthreads();

        // S = Q K^T (single fp16 term, pre-scaled log2 domain)
        float sc[8][4] = {};
#pragma unroll
        for (int kd = 0; kd < 4; kd++) {
            const int colb = kd * 16 + (lane >> 4) * 8;
            uint32_t kb[8][2];
#pragma unroll
            for (int p = 0; p < 4; p++) {
                int row = p * 16 + (lane & 15);
                uint32_t tt[4];
                ldsm4(tt, &ks[row][colb]);
                kb[2 * p][0] = tt[0]; kb[2 * p][1] = tt[2];
                kb[2 * p + 1][0] = tt[1]; kb[2 * p + 1][1] = tt[3];
            }
#pragma unroll
            for (int nt = 0; nt < 8; nt++)
                mma_f16(sc[nt], qh[kd], kb[nt]);
        }

        // Online softmax (base-2)
        float mx0 = -1e30f, mx1 = -1e30f;
#pragma unroll
        for (int nt = 0; nt < 8; nt++) {
            mx0 = fmaxf(mx0, fmaxf(sc[nt][0], sc[nt][1]));
            mx1 = fmaxf(mx1, fmaxf(sc[nt][2], sc[nt][3]));
        }
        mx0 = fmaxf(mx0, __shfl_xor_sync(0xffffffffu, mx0, 1));
        mx0 = fmaxf(mx0, __shfl_xor_sync(0xffffffffu, mx0, 2));
        mx1 = fmaxf(mx1, __shfl_xor_sync(0xffffffffu, mx1, 1));
        mx1 = fmaxf(mx1, __shfl_xor_sync(0xffffffffu, mx1, 2));
        float mn0 = fmaxf(m0, mx0), mn1 = fmaxf(m1, mx1);
        float a0 = ex2f(m0 - mn0), a1 = ex2f(m1 - mn1);
        m0 = mn0; m1 = mn1;

        float sum0 = 0.f, sum1 = 0.f;
#pragma unroll
        for (int nt = 0; nt < 8; nt++) {
            sc[nt][0] = ex2f(sc[nt][0] - mn0);
            sc[nt][1] = ex2f(sc[nt][1] - mn0);
            sc[nt][2] = ex2f(sc[nt][2] - mn1);
            sc[nt][3] = ex2f(sc[nt][3] - mn1);
            sum0 += sc[nt][0] + sc[nt][1];
            sum1 += sc[nt][2] + sc[nt][3];
        }
        sum0 += __shfl_xor_sync(0xffffffffu, sum0, 1);
        sum0 += __shfl_xor_sync(0xffffffffu, sum0, 2);
        sum1 += __shfl_xor_sync(0xffffffffu, sum1, 1);
        sum1 += __shfl_xor_sync(0xffffffffu, sum1, 2);
        l0 = l0 * a0 + sum0;
        l1 = l1 * a1 + sum1;
#pragma unroll
        for (int nd = 0; nd < 8; nd++) {
            o[nd][0] *= a0; o[nd][1] *= a0;
            o[nd][2] *= a1; o[nd][3] *= a1;
        }

        // P fragments, single fp16
        uint32_t pa[4][4];
#pragma unroll
        for (int kt = 0; kt < 4; kt++) {
            pa[kt][0] = pack2h(sc[2 * kt][0], sc[2 * kt][1]);
            pa[kt][1] = pack2h(sc[2 * kt][2], sc[2 * kt][3]);
            pa[kt][2] = pack2h(sc[2 * kt + 1][0], sc[2 * kt + 1][1]);
            pa[kt][3] = pack2h(sc[2 * kt + 1][2], sc[2 * kt + 1][3]);
        }

        // O += P V (single term)
#pragma unroll
        for (int kt = 0; kt < 4; kt++) {
            const int colb = kt * 16 + (lane >> 4) * 8;
            uint32_t vb[8][2];
#pragma unroll
            for (int p = 0; p < 4; p++) {
                int row = p * 16 + (lane & 15);
                uint32_t tt[4];
                ldsm4(tt, &vs[row][colb]);
                vb[2 * p][0] = tt[0]; vb[2 * p][1] = tt[2];
                vb[2 * p + 1][0] = tt[1]; vb[2 * p + 1][1] = tt[3];
            }
#pragma unroll
            for (int nd = 0; nd < 8; nd++)
                mma_f16(o[nd], pa[kt], vb[nd]);
        }
    }

    // Epilogue: normalize, pack to single fp16 for 1-term out-projection
    float i0 = 1.f / l0, i1 = 1.f / l1;
    int b = bh >> 4, h = bh & 15;
    int r0 = b * N_ + qb * 128 + w * 16 + (lane >> 2);
#pragma unroll
    for (int nd = 0; nd < 8; nd++) {
        int col = h * 64 + nd * 8 + 2 * (lane & 3);
        *(uint32_t*)(Of + (size_t)r0 * E_ + col) = pack2h(o[nd][0] * i0, o[nd][1] * i0);
        *(uint32_t*)(Of + (size_t)(r0 + 8) * E_ + col) = pack2h(o[nd][2] * i1, o[nd][3] * i1);
    }
}

// ---------------------------------------------------------------------------
extern "C" void kernel_launch(void* const* d_in, const int* in_sizes, int n_in,
                              void* d_out, int out_size) {
    (void)in_sizes; (void)n_in; (void)out_size;
    const float* x     = (const float*)d_in[0];
    const float* W_qkv = (const float*)d_in[1];
    const float* b_qkv = (const float*)d_in[2];
    const float* W_out = (const float*)d_in[3];
    const float* b_out = (const float*)d_in[4];
    float* out = (float*)d_out;

    __half *wq, *wo, *xf, *q_f, *k_f, *v_t, *o_f;
    float* qkv;
    cudaGetSymbolAddress((void**)&wq, g_wqkv);
    cudaGetSymbolAddress((void**)&wo, g_wout);
    cudaGetSymbolAddress((void**)&xf, g_xf);
    cudaGetSymbolAddress((void**)&qkv, g_qkv);
    cudaGetSymbolAddress((void**)&q_f, g_qf);
    cudaGetSymbolAddress((void**)&k_f, g_kf);
    cudaGetSymbolAddress((void**)&v_t, g_vt);
    cudaGetSymbolAddress((void**)&o_f, g_of);

    // Prep: cast x to fp16, transpose both weights to fp16
    cast_x_kernel<<<(M_TOT * E_ / 4 + 255) / 256, 256>>>((const float4*)x, xf,
                                                         M_TOT * E_ / 4);
    transpose_f16_kernel<<<dim3(QKV_N / 32, E_ / 32), 256>>>(W_qkv, wq, E_, QKV_N);
    transpose_f16_kernel<<<dim3(E_ / 32, E_ / 32), 256>>>(W_out, wo, E_, E_);

    // QKV projection (single-term fp16, f32 out)
    gemm_1t_kernel<<<dim3(QKV_N / 128, M_TOT / 128), 256>>>(
        xf, wq, b_qkv, qkv, M_TOT, QKV_N, E_);

    // Repack into per-head fp16 layouts
    repack_kernel<<<dim3(N_ / 64, BH_), 256>>>(qkv, q_f, k_f, v_t);

    // Attention (single-term QK, single-term PV, fp16 out)
    attn_kernel<<<dim3(N_ / 128, BH_), 256>>>(q_f, k_f, v_t, o_f);

    // Output projection (single-term fp16)
    gemm_1t_kernel<<<dim3(E_ / 128, M_TOT / 128), 256>>>(
        o_f, wo, b_out, out, M_TOT, E_, E_);
}

// round 15
// speedup vs baseline: 2.2969x; 1.0228x over previous
#include <cuda_runtime.h>
#include <cuda_bf16.h>
#include <cuda_fp16.h>
#include <stdint.h>

// Problem constants
#define B_   2
#define N_   2048
#define E_   1024
#define H_   16
#define HD_  64
#define M_TOT  (B_ * N_)     // 4096
#define QKV_N  (3 * E_)      // 3072
#define BH_    (B_ * H_)     // 32

// ---------------------------------------------------------------------------
// Device scratch (allocation-free rule)
// ---------------------------------------------------------------------------
__device__ __half g_wqkv[(size_t)QKV_N * E_];   // W_qkv^T fp16
__device__ __half g_wout[(size_t)E_ * E_];      // W_out^T fp16
__device__ __half g_xf[(size_t)M_TOT * E_];     // x fp16 single
__device__ __half g_qkv[(size_t)M_TOT * QKV_N]; // qkv intermediate (fp16 now)
__device__ __half g_qf[(size_t)BH_ * N_ * HD_];
__device__ __half g_kf[(size_t)BH_ * N_ * HD_];
__device__ __half g_vt[(size_t)BH_ * HD_ * N_];
__device__ __half g_of[(size_t)M_TOT * E_];     // attn out fp16 single

// ---------------------------------------------------------------------------
// Helpers
// ---------------------------------------------------------------------------
__device__ __forceinline__ uint32_t smem_u32(const void* p) {
    uint32_t a;
    asm("{ .reg .u64 t; cvta.to.shared.u64 t, %1; cvt.u32.u64 %0, t; }"
        : "=r"(a) : "l"(p));
    return a;
}

__device__ __forceinline__ void mma_f16(float c[4], const uint32_t a[4],
                                        const uint32_t b[2]) {
    asm volatile(
        "mma.sync.aligned.m16n8k16.row.col.f32.f16.f16.f32 "
        "{%0,%1,%2,%3},{%4,%5,%6,%7},{%8,%9},{%0,%1,%2,%3};"
        : "+f"(c[0]), "+f"(c[1]), "+f"(c[2]), "+f"(c[3])
        : "r"(a[0]), "r"(a[1]), "r"(a[2]), "r"(a[3]), "r"(b[0]), "r"(b[1]));
}

__device__ __forceinline__ void ldsm4(uint32_t r[4], const void* p) {
    uint32_t a = smem_u32(p);
    asm volatile("ldmatrix.sync.aligned.m8n8.x4.shared.b16 {%0,%1,%2,%3},[%4];"
                 : "=r"(r[0]), "=r"(r[1]), "=r"(r[2]), "=r"(r[3])
                 : "r"(a));
}

__device__ __forceinline__ void cpa16(uint32_t s, const void* g) {
    asm volatile("cp.async.cg.shared.global [%0],[%1],16;" ::"r"(s), "l"(g));
}

__device__ __forceinline__ float ex2f(float x) {
    float r;
    asm("ex2.approx.ftz.f32 %0,%1;" : "=f"(r) : "f"(x));
    return r;
}

// Pack two floats to fp16x2
__device__ __forceinline__ uint32_t pack2h(float x, float y) {
    __half2 t = __floats2half2_rn(x, y);
    return *reinterpret_cast<uint32_t*>(&t);
}

// ---------------------------------------------------------------------------
// 1) Elementwise cast of x -> fp16 single
// ---------------------------------------------------------------------------
__global__ void cast_x_kernel(const float4* __restrict__ X,
                              __half* __restrict__ Xf, int n4) {
    int i = blockIdx.x * blockDim.x + threadIdx.x;
    if (i >= n4) return;
    float4 v = X[i];
    *(uint32_t*)(Xf + (size_t)i * 4)     = pack2h(v.x, v.y);
    *(uint32_t*)(Xf + (size_t)i * 4 + 2) = pack2h(v.z, v.w);
}

// ---------------------------------------------------------------------------
// 2) Transpose W[K,N] -> Wt fp16 single [N,K]
// ---------------------------------------------------------------------------
__global__ void transpose_f16_kernel(const float* __restrict__ W,
                                     __half* __restrict__ T, int K, int N) {
    __shared__ float t[32][33];
    int k0 = blockIdx.y * 32, n0 = blockIdx.x * 32;
    int tx = threadIdx.x & 31, ty = threadIdx.x >> 5;
#pragma unroll
    for (int i = 0; i < 4; i++)
        t[ty + 8 * i][tx] = W[(size_t)(k0 + ty + 8 * i) * N + n0 + tx];
    __syncthreads();
#pragma unroll
    for (int i = 0; i < 4; i++)
        T[(size_t)(n0 + ty + 8 * i) * K + k0 + tx] = __float2half_rn(t[tx][ty + 8 * i]);
}

// ---------------------------------------------------------------------------
// 3a) Single-term fp16 GEMM, fp16 output (QKV projection).
//     3-stage cp.async pipeline, ONE sync per iteration.
// ---------------------------------------------------------------------------
__global__ __launch_bounds__(256)
void gemm_1t_h_kernel(const __half* __restrict__ Af, const __half* __restrict__ Bf,
                      const float* __restrict__ bias,
                      __half* __restrict__ C, int M, int N, int K) {
    __shared__ __half sm[3][2][128][24];  // 36KB; 3 stages x {A,B}
    const int tid = threadIdx.x, lane = tid & 31, w = tid >> 5;
    const int wm = w >> 2, wn = w & 3;    // 2 x 4 warp grid
    const int brow = blockIdx.y * 128, bcol = blockIdx.x * 128;

    float c[4][4][4] = {};

    auto load_stage = [&](int s, int k0) {
#pragma unroll
        for (int i = 0; i < 2; i++) {
            int ch = tid + i * 256;   // 0..511
            int arr = ch >> 8;
            int r = (ch & 255) >> 1;
            int h8 = (ch & 1) * 8;
            const __half* g;
            if (arr == 0) g = Af + (size_t)(brow + r) * K + k0 + h8;
            else          g = Bf + (size_t)(bcol + r) * K + k0 + h8;
            cpa16(smem_u32(&sm[s][arr][r][h8]), g);
        }
        asm volatile("cp.async.commit_group;");
    };

    const int NIT = K >> 4;               // 64
    load_stage(0, 0);
    load_stage(1, 16);
    for (int it = 0; it < NIT; ++it) {
        const int s = it % 3;
        if (it + 1 < NIT)
            asm volatile("cp.async.wait_group 1;");
        else
            asm volatile("cp.async.wait_group 0;");
        __syncthreads();   // all warps done reading stage (it-1)%3 == (it+2)%3
        if (it + 2 < NIT) load_stage((it + 2) % 3, (it + 2) * 16);

        uint32_t af[4][4];
#pragma unroll
        for (int mt = 0; mt < 4; mt++) {
            int row = wm * 64 + mt * 16 + (lane & 15);
            int col = (lane >> 4) * 8;
            ldsm4(af[mt], &sm[s][0][row][col]);
        }
        uint32_t bf[4][2];
#pragma unroll
        for (int p = 0; p < 2; p++) {
            int row = wn * 32 + p * 16 + (lane & 15);
            int col = (lane >> 4) * 8;
            uint32_t t[4];
            ldsm4(t, &sm[s][1][row][col]);
            bf[2 * p][0] = t[0]; bf[2 * p][1] = t[2];
            bf[2 * p + 1][0] = t[1]; bf[2 * p + 1][1] = t[3];
        }
#pragma unroll
        for (int mt = 0; mt < 4; mt++)
#pragma unroll
            for (int nt = 0; nt < 4; nt++)
                mma_f16(c[mt][nt], af[mt], bf[nt]);
    }

    // Epilogue: bias, pack to fp16
#pragma unroll
    for (int mt = 0; mt < 4; mt++) {
        int r0 = brow + wm * 64 + mt * 16 + (lane >> 2);
#pragma unroll
        for (int nt = 0; nt < 4; nt++) {
            int col = bcol + wn * 32 + nt * 8 + 2 * (lane & 3);
            float b0 = bias[col], b1 = bias[col + 1];
            *(uint32_t*)(C + (size_t)r0 * N + col) =
                pack2h(c[mt][nt][0] + b0, c[mt][nt][1] + b1);
            *(uint32_t*)(C + (size_t)(r0 + 8) * N + col) =
                pack2h(c[mt][nt][2] + b0, c[mt][nt][3] + b1);
        }
    }
}

// ---------------------------------------------------------------------------
// 3b) Single-term fp16 GEMM, f32 output (out-projection). Same 3-stage pipe.
// ---------------------------------------------------------------------------
__global__ __launch_bounds__(256)
void gemm_1t_kernel(const __half* __restrict__ Af, const __half* __restrict__ Bf,
                    const float* __restrict__ bias,
                    float* __restrict__ C, int M, int N, int K) {
    __shared__ __half sm[3][2][128][24];
    const int tid = threadIdx.x, lane = tid & 31, w = tid >> 5;
    const int wm = w >> 2, wn = w & 3;
    const int brow = blockIdx.y * 128, bcol = blockIdx.x * 128;

    float c[4][4][4] = {};

    auto load_stage = [&](int s, int k0) {
#pragma unroll
        for (int i = 0; i < 2; i++) {
            int ch = tid + i * 256;
            int arr = ch >> 8;
            int r = (ch & 255) >> 1;
            int h8 = (ch & 1) * 8;
            const __half* g;
            if (arr == 0) g = Af + (size_t)(brow + r) * K + k0 + h8;
            else          g = Bf + (size_t)(bcol + r) * K + k0 + h8;
            cpa16(smem_u32(&sm[s][arr][r][h8]), g);
        }
        asm volatile("cp.async.commit_group;");
    };

    const int NIT = K >> 4;
    load_stage(0, 0);
    load_stage(1, 16);
    for (int it = 0; it < NIT; ++it) {
        const int s = it % 3;
        if (it + 1 < NIT)
            asm volatile("cp.async.wait_group 1;");
        else
            asm volatile("cp.async.wait_group 0;");
        __syncthreads();
        if (it + 2 < NIT) load_stage((it + 2) % 3, (it + 2) * 16);

        uint32_t af[4][4];
#pragma unroll
        for (int mt = 0; mt < 4; mt++) {
            int row = wm * 64 + mt * 16 + (lane & 15);
            int col = (lane >> 4) * 8;
            ldsm4(af[mt], &sm[s][0][row][col]);
        }
        uint32_t bf[4][2];
#pragma unroll
        for (int p = 0; p < 2; p++) {
            int row = wn * 32 + p * 16 + (lane & 15);
            int col = (lane >> 4) * 8;
            uint32_t t[4];
            ldsm4(t, &sm[s][1][row][col]);
            bf[2 * p][0] = t[0]; bf[2 * p][1] = t[2];
            bf[2 * p + 1][0] = t[1]; bf[2 * p + 1][1] = t[3];
        }
#pragma unroll
        for (int mt = 0; mt < 4; mt++)
#pragma unroll
            for (int nt = 0; nt < 4; nt++)
                mma_f16(c[mt][nt], af[mt], bf[nt]);
    }

#pragma unroll
    for (int mt = 0; mt < 4; mt++) {
        int r0 = brow + wm * 64 + mt * 16 + (lane >> 2);
#pragma unroll
        for (int nt = 0; nt < 4; nt++) {
            int col = bcol + wn * 32 + nt * 8 + 2 * (lane & 3);
            float b0 = bias[col], b1 = bias[col + 1];
            float2 v0 = {c[mt][nt][0] + b0, c[mt][nt][1] + b1};
            float2 v1 = {c[mt][nt][2] + b0, c[mt][nt][3] + b1};
            *(float2*)(C + (size_t)r0 * N + col) = v0;
            *(float2*)(C + (size_t)(r0 + 8) * N + col) = v1;
        }
    }
}

// ---------------------------------------------------------------------------
// 4) Repack qkv fp16 -> per-head Q(scaled)/K fp16, V^T fp16
// ---------------------------------------------------------------------------
__global__ __launch_bounds__(256)
void repack_kernel(const __half* __restrict__ qkv,
                   __half* __restrict__ Qf, __half* __restrict__ Kf,
                   __half* __restrict__ Vt) {
    __shared__ __half vt[64][66];
    const int bh = blockIdx.y;
    const int b = bh >> 4, h = bh & 15;
    const int nb = blockIdx.x * 64;
    const float qscale = 0.125f * 1.4426950408889634f;  // scale * log2(e)

    for (int idx = threadIdx.x; idx < 64 * 192; idx += 256) {
        int r = idx / 192, cc = idx % 192;
        __half v = qkv[(size_t)(b * N_ + nb + r) * QKV_N + h * 192 + cc];
        if (cc < 64) {
            Qf[((size_t)bh * N_ + nb + r) * 64 + cc] =
                __float2half_rn(__half2float(v) * qscale);
        } else if (cc < 128) {
            Kf[((size_t)bh * N_ + nb + r) * 64 + (cc - 64)] = v;
        } else {
            vt[cc - 128][r] = v;
        }
    }
    __syncthreads();
    for (int idx = threadIdx.x; idx < 64 * 64; idx += 256) {
        int d = idx >> 6, nl = idx & 63;
        Vt[((size_t)bh * 64 + d) * N_ + nb + nl] = vt[d][nl];
    }
}

// ---------------------------------------------------------------------------
// 5) FA2 attention (EXACT R13/R14): single fp16 QK, single-term PV,
//    fp16-single output.
// ---------------------------------------------------------------------------
__global__ __launch_bounds__(256)
void attn_kernel(const __half* __restrict__ Qf, const __half* __restrict__ Kf,
                 const __half* __restrict__ Vt,
                 __half* __restrict__ Of) {
    __shared__ __half ks[64][72];       // K tile [key][d]
    __shared__ __half vs[64][72];       // V tile, transposed [d][key]
    const int tid = threadIdx.x, lane = tid & 31, w = tid >> 5;
    const int bh = blockIdx.y, qb = blockIdx.x;
    const size_t qkbase = (size_t)bh * N_ * 64;
    const size_t vbase = (size_t)bh * 64 * N_;

    // Q fragments (fp16, pre-scaled) held in registers
    uint32_t qh[4][4];
    {
        int r0 = qb * 128 + w * 16 + (lane >> 2);
        int c0 = 2 * (lane & 3);
#pragma unroll
        for (int kd = 0; kd < 4; kd++) {
            const __half* ph = Qf + qkbase + (size_t)r0 * 64 + kd * 16 + c0;
            qh[kd][0] = *(const uint32_t*)(ph);
            qh[kd][1] = *(const uint32_t*)(ph + 8 * 64);
            qh[kd][2] = *(const uint32_t*)(ph + 8);
            qh[kd][3] = *(const uint32_t*)(ph + 8 * 64 + 8);
        }
    }

    float m0 = -1e30f, m1 = -1e30f, l0 = 0.f, l1 = 0.f;
    float o[8][4] = {};

    for (int kt0 = 0; kt0 < N_; kt0 += 64) {
        __syncthreads();
        // Load K (512 float4) + V (512) = 1024 chunks, 4/thread
#pragma unroll
        for (int i = 0; i < 4; i++) {
            int ch = tid + i * 256;
            int arr = ch >> 9;
            int rem = ch & 511;
            int r = rem >> 3;
            int h8 = (rem & 7) * 8;
            if (arr == 0)
                *(float4*)&ks[r][h8] = *(const float4*)(Kf + qkbase + (size_t)(kt0 + r) * 64 + h8);
            else
                *(float4*)&vs[r][h8] = *(const float4*)(Vt + vbase + (size_t)r * N_ + kt0 + h8);
        }
        __syncthreads();

        // S = Q K^T (single fp16 term, pre-scaled log2 domain)
        float sc[8][4] = {};
#pragma unroll
        for (int kd = 0; kd < 4; kd++) {
            const int colb = kd * 16 + (lane >> 4) * 8;
            uint32_t kb[8][2];
#pragma unroll
            for (int p = 0; p < 4; p++) {
                int row = p * 16 + (lane & 15);
                uint32_t tt[4];
                ldsm4(tt, &ks[row][colb]);
                kb[2 * p][0] = tt[0]; kb[2 * p][1] = tt[2];
                kb[2 * p + 1][0] = tt[1]; kb[2 * p + 1][1] = tt[3];
            }
#pragma unroll
            for (int nt = 0; nt < 8; nt++)
                mma_f16(sc[nt], qh[kd], kb[nt]);
        }

        // Online softmax (base-2)
        float mx0 = -1e30f, mx1 = -1e30f;
#pragma unroll
        for (int nt = 0; nt < 8; nt++) {
            mx0 = fmaxf(mx0, fmaxf(sc[nt][0], sc[nt][1]));
            mx1 = fmaxf(mx1, fmaxf(sc[nt][2], sc[nt][3]));
        }
        mx0 = fmaxf(mx0, __shfl_xor_sync(0xffffffffu, mx0, 1));
        mx0 = fmaxf(mx0, __shfl_xor_sync(0xffffffffu, mx0, 2));
        mx1 = fmaxf(mx1, __shfl_xor_sync(0xffffffffu, mx1, 1));
        mx1 = fmaxf(mx1, __shfl_xor_sync(0xffffffffu, mx1, 2));
        float mn0 = fmaxf(m0, mx0), mn1 = fmaxf(m1, mx1);
        float a0 = ex2f(m0 - mn0), a1 = ex2f(m1 - mn1);
        m0 = mn0; m1 = mn1;

        float sum0 = 0.f, sum1 = 0.f;
#pragma unroll
        for (int nt = 0; nt < 8; nt++) {
            sc[nt][0] = ex2f(sc[nt][0] - mn0);
            sc[nt][1] = ex2f(sc[nt][1] - mn0);
            sc[nt][2] = ex2f(sc[nt][2] - mn1);
            sc[nt][3] = ex2f(sc[nt][3] - mn1);
            sum0 += sc[nt][0] + sc[nt][1];
            sum1 += sc[nt][2] + sc[nt][3];
        }
        sum0 += __shfl_xor_sync(0xffffffffu, sum0, 1);
        sum0 += __shfl_xor_sync(0xffffffffu, sum0, 2);
        sum1 += __shfl_xor_sync(0xffffffffu, sum1, 1);
        sum1 += __shfl_xor_sync(0xffffffffu, sum1, 2);
        l0 = l0 * a0 + sum0;
        l1 = l1 * a1 + sum1;
#pragma unroll
        for (int nd = 0; nd < 8; nd++) {
            o[nd][0] *= a0; o[nd][1] *= a0;
            o[nd][2] *= a1; o[nd][3] *= a1;
        }

        // P fragments, single fp16
        uint32_t pa[4][4];
#pragma unroll
        for (int kt = 0; kt < 4; kt++) {
            pa[kt][0] = pack2h(sc[2 * kt][0], sc[2 * kt][1]);
            pa[kt][1] = pack2h(sc[2 * kt][2], sc[2 * kt][3]);
            pa[kt][2] = pack2h(sc[2 * kt + 1][0], sc[2 * kt + 1][1]);
            pa[kt][3] = pack2h(sc[2 * kt + 1][2], sc[2 * kt + 1][3]);
        }

        // O += P V (single term)
#pragma unroll
        for (int kt = 0; kt < 4; kt++) {
            const int colb = kt * 16 + (lane >> 4) * 8;
            uint32_t vb[8][2];
#pragma unroll
            for (int p = 0; p < 4; p++) {
                int row = p * 16 + (lane & 15);
                uint32_t tt[4];
                ldsm4(tt, &vs[row][colb]);
                vb[2 * p][0] = tt[0]; vb[2 * p][1] = tt[2];
                vb[2 * p + 1][0] = tt[1]; vb[2 * p + 1][1] = tt[3];
            }
#pragma unroll
            for (int nd = 0; nd < 8; nd++)
                mma_f16(o[nd], pa[kt], vb[nd]);
        }
    }

    // Epilogue: normalize, pack to single fp16 for 1-term out-projection
    float i0 = 1.f / l0, i1 = 1.f / l1;
    int b = bh >> 4, h = bh & 15;
    int r0 = b * N_ + qb * 128 + w * 16 + (lane >> 2);
#pragma unroll
    for (int nd = 0; nd < 8; nd++) {
        int col = h * 64 + nd * 8 + 2 * (lane & 3);
        *(uint32_t*)(Of + (size_t)r0 * E_ + col) = pack2h(o[nd][0] * i0, o[nd][1] * i0);
        *(uint32_t*)(Of + (size_t)(r0 + 8) * E_ + col) = pack2h(o[nd][2] * i1, o[nd][3] * i1);
    }
}

// ---------------------------------------------------------------------------
extern "C" void kernel_launch(void* const* d_in, const int* in_sizes, int n_in,
                              void* d_out, int out_size) {
    (void)in_sizes; (void)n_in; (void)out_size;
    const float* x     = (const float*)d_in[0];
    const float* W_qkv = (const float*)d_in[1];
    const float* b_qkv = (const float*)d_in[2];
    const float* W_out = (const float*)d_in[3];
    const float* b_out = (const float*)d_in[4];
    float* out = (float*)d_out;

    __half *wq, *wo, *xf, *qkv, *q_f, *k_f, *v_t, *o_f;
    cudaGetSymbolAddress((void**)&wq, g_wqkv);
    cudaGetSymbolAddress((void**)&wo, g_wout);
    cudaGetSymbolAddress((void**)&xf, g_xf);
    cudaGetSymbolAddress((void**)&qkv, g_qkv);
    cudaGetSymbolAddress((void**)&q_f, g_qf);
    cudaGetSymbolAddress((void**)&k_f, g_kf);
    cudaGetSymbolAddress((void**)&v_t, g_vt);
    cudaGetSymbolAddress((void**)&o_f, g_of);

    // Prep: cast x to fp16, transpose both weights to fp16
    cast_x_kernel<<<(M_TOT * E_ / 4 + 255) / 256, 256>>>((const float4*)x, xf,
                                                         M_TOT * E_ / 4);
    transpose_f16_kernel<<<dim3(QKV_N / 32, E_ / 32), 256>>>(W_qkv, wq, E_, QKV_N);
    transpose_f16_kernel<<<dim3(E_ / 32, E_ / 32), 256>>>(W_out, wo, E_, E_);

    // QKV projection (single-term fp16, fp16 out, 3-stage pipe)
    gemm_1t_h_kernel<<<dim3(QKV_N / 128, M_TOT / 128), 256>>>(
        xf, wq, b_qkv, qkv, M_TOT, QKV_N, E_);

    // Repack into per-head fp16 layouts
    repack_kernel<<<dim3(N_ / 64, BH_), 256>>>(qkv, q_f, k_f, v_t);

    // Attention (single-term QK, single-term PV, fp16 out)
    attn_kernel<<<dim3(N_ / 128, BH_), 256>>>(q_f, k_f, v_t, o_f);

    // Output projection (single-term fp16, f32 out, 3-stage pipe)
    gemm_1t_kernel<<<dim3(E_ / 128, M_TOT / 128), 256>>>(
        o_f, wo, b_out, out, M_TOT, E_, E_);
}

// round 17
// speedup vs baseline: 2.3467x; 1.0217x over previous
#include <cuda_runtime.h>
#include <cuda_bf16.h>
#include <cuda_fp16.h>
#include <stdint.h>

// Problem constants
#define B_   2
#define N_   2048
#define E_   1024
#define H_   16
#define HD_  64
#define M_TOT  (B_ * N_)     // 4096
#define QKV_N  (3 * E_)      // 3072
#define BH_    (B_ * H_)     // 32

// ---------------------------------------------------------------------------
// Device scratch (allocation-free rule)
// ---------------------------------------------------------------------------
__device__ __half g_wqkv[(size_t)QKV_N * E_];   // W_qkv^T fp16
__device__ __half g_wout[(size_t)E_ * E_];      // W_out^T fp16
__device__ __half g_xf[(size_t)M_TOT * E_];     // x fp16 single
__device__ __half g_qkv[(size_t)M_TOT * QKV_N]; // qkv intermediate fp16
__device__ __half g_qf[(size_t)BH_ * N_ * HD_];
__device__ __half g_kf[(size_t)BH_ * N_ * HD_];
__device__ __half g_vt[(size_t)BH_ * HD_ * N_];
__device__ __half g_of[(size_t)M_TOT * E_];     // attn out fp16 single

// ---------------------------------------------------------------------------
// Helpers
// ---------------------------------------------------------------------------
__device__ __forceinline__ uint32_t smem_u32(const void* p) {
    uint32_t a;
    asm("{ .reg .u64 t; cvta.to.shared.u64 t, %1; cvt.u32.u64 %0, t; }"
        : "=r"(a) : "l"(p));
    return a;
}

__device__ __forceinline__ void mma_f16(float c[4], const uint32_t a[4],
                                        const uint32_t b[2]) {
    asm volatile(
        "mma.sync.aligned.m16n8k16.row.col.f32.f16.f16.f32 "
        "{%0,%1,%2,%3},{%4,%5,%6,%7},{%8,%9},{%0,%1,%2,%3};"
        : "+f"(c[0]), "+f"(c[1]), "+f"(c[2]), "+f"(c[3])
        : "r"(a[0]), "r"(a[1]), "r"(a[2]), "r"(a[3]), "r"(b[0]), "r"(b[1]));
}

__device__ __forceinline__ void ldsm4(uint32_t r[4], const void* p) {
    uint32_t a = smem_u32(p);
    asm volatile("ldmatrix.sync.aligned.m8n8.x4.shared.b16 {%0,%1,%2,%3},[%4];"
                 : "=r"(r[0]), "=r"(r[1]), "=r"(r[2]), "=r"(r[3])
                 : "r"(a));
}

__device__ __forceinline__ void cpa16(uint32_t s, const void* g) {
    asm volatile("cp.async.cg.shared.global [%0],[%1],16;" ::"r"(s), "l"(g));
}

__device__ __forceinline__ float ex2f(float x) {
    float r;
    asm("ex2.approx.ftz.f32 %0,%1;" : "=f"(r) : "f"(x));
    return r;
}

// Packed fp16x2 exp2
__device__ __forceinline__ uint32_t h2ex2(uint32_t x) {
    uint32_t r;
    asm("ex2.approx.f16x2 %0,%1;" : "=r"(r) : "r"(x));
    return r;
}

// Pack two floats to fp16x2
__device__ __forceinline__ uint32_t pack2h(float x, float y) {
    __half2 t = __floats2half2_rn(x, y);
    return *reinterpret_cast<uint32_t*>(&t);
}

__device__ __forceinline__ float2 unpack2h(uint32_t v) {
    __half2 h = *reinterpret_cast<__half2*>(&v);
    return __half22float2(h);
}

// ---------------------------------------------------------------------------
// 1) Elementwise cast of x -> fp16 single
// ---------------------------------------------------------------------------
__global__ void cast_x_kernel(const float4* __restrict__ X,
                              __half* __restrict__ Xf, int n4) {
    int i = blockIdx.x * blockDim.x + threadIdx.x;
    if (i >= n4) return;
    float4 v = X[i];
    *(uint32_t*)(Xf + (size_t)i * 4)     = pack2h(v.x, v.y);
    *(uint32_t*)(Xf + (size_t)i * 4 + 2) = pack2h(v.z, v.w);
}

// ---------------------------------------------------------------------------
// 2) Transpose W[K,N] -> Wt fp16 single [N,K]
// ---------------------------------------------------------------------------
__global__ void transpose_f16_kernel(const float* __restrict__ W,
                                     __half* __restrict__ T, int K, int N) {
    __shared__ float t[32][33];
    int k0 = blockIdx.y * 32, n0 = blockIdx.x * 32;
    int tx = threadIdx.x & 31, ty = threadIdx.x >> 5;
#pragma unroll
    for (int i = 0; i < 4; i++)
        t[ty + 8 * i][tx] = W[(size_t)(k0 + ty + 8 * i) * N + n0 + tx];
    __syncthreads();
#pragma unroll
    for (int i = 0; i < 4; i++)
        T[(size_t)(n0 + ty + 8 * i) * K + k0 + tx] = __float2half_rn(t[tx][ty + 8 * i]);
}

// ---------------------------------------------------------------------------
// 3a) Single-term fp16 GEMM, fp16 output. 3-stage pipe, counter-based stages.
// ---------------------------------------------------------------------------
__global__ __launch_bounds__(256)
void gemm_1t_h_kernel(const __half* __restrict__ Af, const __half* __restrict__ Bf,
                      const float* __restrict__ bias,
                      __half* __restrict__ C, int M, int N, int K) {
    __shared__ __half sm[3][2][128][24];  // 36KB; 3 stages x {A,B}
    const int tid = threadIdx.x, lane = tid & 31, w = tid >> 5;
    const int wm = w >> 2, wn = w & 3;
    const int brow = blockIdx.y * 128, bcol = blockIdx.x * 128;

    float c[4][4][4] = {};

    auto load_stage = [&](int s, int k0) {
#pragma unroll
        for (int i = 0; i < 2; i++) {
            int ch = tid + i * 256;
            int arr = ch >> 8;
            int r = (ch & 255) >> 1;
            int h8 = (ch & 1) * 8;
            const __half* g;
            if (arr == 0) g = Af + (size_t)(brow + r) * K + k0 + h8;
            else          g = Bf + (size_t)(bcol + r) * K + k0 + h8;
            cpa16(smem_u32(&sm[s][arr][r][h8]), g);
        }
        asm volatile("cp.async.commit_group;");
    };

    const int NIT = K >> 4;
    load_stage(0, 0);
    load_stage(1, 16);
    int s = 0, ls = 2;
    for (int it = 0; it < NIT; ++it) {
        if (it + 1 < NIT)
            asm volatile("cp.async.wait_group 1;");
        else
            asm volatile("cp.async.wait_group 0;");
        __syncthreads();
        if (it + 2 < NIT) {
            load_stage(ls, (it + 2) * 16);
            if (++ls == 3) ls = 0;
        }

        uint32_t af[4][4];
#pragma unroll
        for (int mt = 0; mt < 4; mt++) {
            int row = wm * 64 + mt * 16 + (lane & 15);
            int col = (lane >> 4) * 8;
            ldsm4(af[mt], &sm[s][0][row][col]);
        }
        uint32_t bf[4][2];
#pragma unroll
        for (int p = 0; p < 2; p++) {
            int row = wn * 32 + p * 16 + (lane & 15);
            int col = (lane >> 4) * 8;
            uint32_t t[4];
            ldsm4(t, &sm[s][1][row][col]);
            bf[2 * p][0] = t[0]; bf[2 * p][1] = t[2];
            bf[2 * p + 1][0] = t[1]; bf[2 * p + 1][1] = t[3];
        }
#pragma unroll
        for (int mt = 0; mt < 4; mt++)
#pragma unroll
            for (int nt = 0; nt < 4; nt++)
                mma_f16(c[mt][nt], af[mt], bf[nt]);
        if (++s == 3) s = 0;
    }

#pragma unroll
    for (int mt = 0; mt < 4; mt++) {
        int r0 = brow + wm * 64 + mt * 16 + (lane >> 2);
#pragma unroll
        for (int nt = 0; nt < 4; nt++) {
            int col = bcol + wn * 32 + nt * 8 + 2 * (lane & 3);
            float b0 = bias[col], b1 = bias[col + 1];
            *(uint32_t*)(C + (size_t)r0 * N + col) =
                pack2h(c[mt][nt][0] + b0, c[mt][nt][1] + b1);
            *(uint32_t*)(C + (size_t)(r0 + 8) * N + col) =
                pack2h(c[mt][nt][2] + b0, c[mt][nt][3] + b1);
        }
    }
}

// ---------------------------------------------------------------------------
// 3b) Single-term fp16 GEMM, f32 output. Same 3-stage pipe.
// ---------------------------------------------------------------------------
__global__ __launch_bounds__(256)
void gemm_1t_kernel(const __half* __restrict__ Af, const __half* __restrict__ Bf,
                    const float* __restrict__ bias,
                    float* __restrict__ C, int M, int N, int K) {
    __shared__ __half sm[3][2][128][24];
    const int tid = threadIdx.x, lane = tid & 31, w = tid >> 5;
    const int wm = w >> 2, wn = w & 3;
    const int brow = blockIdx.y * 128, bcol = blockIdx.x * 128;

    float c[4][4][4] = {};

    auto load_stage = [&](int s, int k0) {
#pragma unroll
        for (int i = 0; i < 2; i++) {
            int ch = tid + i * 256;
            int arr = ch >> 8;
            int r = (ch & 255) >> 1;
            int h8 = (ch & 1) * 8;
            const __half* g;
            if (arr == 0) g = Af + (size_t)(brow + r) * K + k0 + h8;
            else          g = Bf + (size_t)(bcol + r) * K + k0 + h8;
            cpa16(smem_u32(&sm[s][arr][r][h8]), g);
        }
        asm volatile("cp.async.commit_group;");
    };

    const int NIT = K >> 4;
    load_stage(0, 0);
    load_stage(1, 16);
    int s = 0, ls = 2;
    for (int it = 0; it < NIT; ++it) {
        if (it + 1 < NIT)
            asm volatile("cp.async.wait_group 1;");
        else
            asm volatile("cp.async.wait_group 0;");
        __syncthreads();
        if (it + 2 < NIT) {
            load_stage(ls, (it + 2) * 16);
            if (++ls == 3) ls = 0;
        }

        uint32_t af[4][4];
#pragma unroll
        for (int mt = 0; mt < 4; mt++) {
            int row = wm * 64 + mt * 16 + (lane & 15);
            int col = (lane >> 4) * 8;
            ldsm4(af[mt], &sm[s][0][row][col]);
        }
        uint32_t bf[4][2];
#pragma unroll
        for (int p = 0; p < 2; p++) {
            int row = wn * 32 + p * 16 + (lane & 15);
            int col = (lane >> 4) * 8;
            uint32_t t[4];
            ldsm4(t, &sm[s][1][row][col]);
            bf[2 * p][0] = t[0]; bf[2 * p][1] = t[2];
            bf[2 * p + 1][0] = t[1]; bf[2 * p + 1][1] = t[3];
        }
#pragma unroll
        for (int mt = 0; mt < 4; mt++)
#pragma unroll
            for (int nt = 0; nt < 4; nt++)
                mma_f16(c[mt][nt], af[mt], bf[nt]);
        if (++s == 3) s = 0;
    }

#pragma unroll
    for (int mt = 0; mt < 4; mt++) {
        int r0 = brow + wm * 64 + mt * 16 + (lane >> 2);
#pragma unroll
        for (int nt = 0; nt < 4; nt++) {
            int col = bcol + wn * 32 + nt * 8 + 2 * (lane & 3);
            float b0 = bias[col], b1 = bias[col + 1];
            float2 v0 = {c[mt][nt][0] + b0, c[mt][nt][1] + b1};
            float2 v1 = {c[mt][nt][2] + b0, c[mt][nt][3] + b1};
            *(float2*)(C + (size_t)r0 * N + col) = v0;
            *(float2*)(C + (size_t)(r0 + 8) * N + col) = v1;
        }
    }
}

// ---------------------------------------------------------------------------
// 4) Repack qkv fp16 -> per-head Q(scaled)/K fp16, V^T fp16
// ---------------------------------------------------------------------------
__global__ __launch_bounds__(256)
void repack_kernel(const __half* __restrict__ qkv,
                   __half* __restrict__ Qf, __half* __restrict__ Kf,
                   __half* __restrict__ Vt) {
    __shared__ __half vt[64][66];
    const int bh = blockIdx.y;
    const int b = bh >> 4, h = bh & 15;
    const int nb = blockIdx.x * 64;
    const float qscale = 0.125f * 1.4426950408889634f;  // scale * log2(e)

    for (int idx = threadIdx.x; idx < 64 * 192; idx += 256) {
        int r = idx / 192, cc = idx % 192;
        __half v = qkv[(size_t)(b * N_ + nb + r) * QKV_N + h * 192 + cc];
        if (cc < 64) {
            Qf[((size_t)bh * N_ + nb + r) * 64 + cc] =
                __float2half_rn(__half2float(v) * qscale);
        } else if (cc < 128) {
            Kf[((size_t)bh * N_ + nb + r) * 64 + (cc - 64)] = v;
        } else {
            vt[cc - 128][r] = v;
        }
    }
    __syncthreads();
    for (int idx = threadIdx.x; idx < 64 * 64; idx += 256) {
        int d = idx >> 6, nl = idx & 63;
        Vt[((size_t)bh * 64 + d) * N_ + nb + nl] = vt[d][nl];
    }
}

// ---------------------------------------------------------------------------
// 5) FA2 attention: single fp16 QK, single-term PV, fp16x2 softmax exp,
//    2-stage cp.async K/V double-buffer.
// ---------------------------------------------------------------------------
__global__ __launch_bounds__(256)
void attn_kernel(const __half* __restrict__ Qf, const __half* __restrict__ Kf,
                 const __half* __restrict__ Vt,
                 __half* __restrict__ Of) {
    __shared__ __half ks[2][64][72];    // K tiles [stage][key][d]
    __shared__ __half vs[2][64][72];    // V tiles [stage][d][key]
    const int tid = threadIdx.x, lane = tid & 31, w = tid >> 5;
    const int bh = blockIdx.y, qb = blockIdx.x;
    const size_t qkbase = (size_t)bh * N_ * 64;
    const size_t vbase = (size_t)bh * 64 * N_;

    auto load_tile = [&](int st, int kt0) {
#pragma unroll
        for (int i = 0; i < 4; i++) {
            int ch = tid + i * 256;
            int arr = ch >> 9;
            int rem = ch & 511;
            int r = rem >> 3;
            int h8 = (rem & 7) * 8;
            if (arr == 0)
                cpa16(smem_u32(&ks[st][r][h8]),
                      Kf + qkbase + (size_t)(kt0 + r) * 64 + h8);
            else
                cpa16(smem_u32(&vs[st][r][h8]),
                      Vt + vbase + (size_t)r * N_ + kt0 + h8);
        }
        asm volatile("cp.async.commit_group;");
    };

    // Q fragments (fp16, pre-scaled) held in registers
    uint32_t qh[4][4];
    {
        int r0 = qb * 128 + w * 16 + (lane >> 2);
        int c0 = 2 * (lane & 3);
#pragma unroll
        for (int kd = 0; kd < 4; kd++) {
            const __half* ph = Qf + qkbase + (size_t)r0 * 64 + kd * 16 + c0;
            qh[kd][0] = *(const uint32_t*)(ph);
            qh[kd][1] = *(const uint32_t*)(ph + 8 * 64);
            qh[kd][2] = *(const uint32_t*)(ph + 8);
            qh[kd][3] = *(const uint32_t*)(ph + 8 * 64 + 8);
        }
    }

    float m0 = -1e30f, m1 = -1e30f, l0 = 0.f, l1 = 0.f;
    float o[8][4] = {};

    const int NT = N_ / 64;
    load_tile(0, 0);

    for (int t = 0; t < NT; ++t) {
        const int st = t & 1;
        asm volatile("cp.async.wait_group 0;");
        __syncthreads();
        if (t + 1 < NT) load_tile(st ^ 1, (t + 1) * 64);

        // S = Q K^T (single fp16 term, pre-scaled log2 domain)
        float sc[8][4] = {};
#pragma unroll
        for (int kd = 0; kd < 4; kd++) {
            const int colb = kd * 16 + (lane >> 4) * 8;
            uint32_t kb[8][2];
#pragma unroll
            for (int p = 0; p < 4; p++) {
                int row = p * 16 + (lane & 15);
                uint32_t tt[4];
                ldsm4(tt, &ks[st][row][colb]);
                kb[2 * p][0] = tt[0]; kb[2 * p][1] = tt[2];
                kb[2 * p + 1][0] = tt[1]; kb[2 * p + 1][1] = tt[3];
            }
#pragma unroll
            for (int nt = 0; nt < 8; nt++)
                mma_f16(sc[nt], qh[kd], kb[nt]);
        }

        // Online softmax (base-2); P computed directly as packed fp16.
        float mx0 = -1e30f, mx1 = -1e30f;
#pragma unroll
        for (int nt = 0; nt < 8; nt++) {
            mx0 = fmaxf(mx0, fmaxf(sc[nt][0], sc[nt][1]));
            mx1 = fmaxf(mx1, fmaxf(sc[nt][2], sc[nt][3]));
        }
        mx0 = fmaxf(mx0, __shfl_xor_sync(0xffffffffu, mx0, 1));
        mx0 = fmaxf(mx0, __shfl_xor_sync(0xffffffffu, mx0, 2));
        mx1 = fmaxf(mx1, __shfl_xor_sync(0xffffffffu, mx1, 1));
        mx1 = fmaxf(mx1, __shfl_xor_sync(0xffffffffu, mx1, 2));
        float mn0 = fmaxf(m0, mx0), mn1 = fmaxf(m1, mx1);
        float a0 = ex2f(m0 - mn0), a1 = ex2f(m1 - mn1);
        m0 = mn0; m1 = mn1;

        // P fragments via f16x2 exp2 (P was fp16 in the PV MMA anyway)
        uint32_t pa[4][4];
        float sum0 = 0.f, sum1 = 0.f;
#pragma unroll
        for (int kt = 0; kt < 4; kt++) {
            pa[kt][0] = h2ex2(pack2h(sc[2 * kt][0] - mn0, sc[2 * kt][1] - mn0));
            pa[kt][1] = h2ex2(pack2h(sc[2 * kt][2] - mn1, sc[2 * kt][3] - mn1));
            pa[kt][2] = h2ex2(pack2h(sc[2 * kt + 1][0] - mn0, sc[2 * kt + 1][1] - mn0));
            pa[kt][3] = h2ex2(pack2h(sc[2 * kt + 1][2] - mn1, sc[2 * kt + 1][3] - mn1));
            float2 f0 = unpack2h(pa[kt][0]);
            float2 f1 = unpack2h(pa[kt][1]);
            float2 f2 = unpack2h(pa[kt][2]);
            float2 f3 = unpack2h(pa[kt][3]);
            sum0 += f0.x + f0.y + f2.x + f2.y;
            sum1 += f1.x + f1.y + f3.x + f3.y;
        }
        sum0 += __shfl_xor_sync(0xffffffffu, sum0, 1);
        sum0 += __shfl_xor_sync(0xffffffffu, sum0, 2);
        sum1 += __shfl_xor_sync(0xffffffffu, sum1, 1);
        sum1 += __shfl_xor_sync(0xffffffffu, sum1, 2);
        l0 = l0 * a0 + sum0;
        l1 = l1 * a1 + sum1;
#pragma unroll
        for (int nd = 0; nd < 8; nd++) {
            o[nd][0] *= a0; o[nd][1] *= a0;
            o[nd][2] *= a1; o[nd][3] *= a1;
        }

        // O += P V (single term)
#pragma unroll
        for (int kt = 0; kt < 4; kt++) {
            const int colb = kt * 16 + (lane >> 4) * 8;
            uint32_t vb[8][2];
#pragma unroll
            for (int p = 0; p < 4; p++) {
                int row = p * 16 + (lane & 15);
                uint32_t tt[4];
                ldsm4(tt, &vs[st][row][colb]);
                vb[2 * p][0] = tt[0]; vb[2 * p][1] = tt[2];
                vb[2 * p + 1][0] = tt[1]; vb[2 * p + 1][1] = tt[3];
            }
#pragma unroll
            for (int nd = 0; nd < 8; nd++)
                mma_f16(o[nd], pa[kt], vb[nd]);
        }
    }

    // Epilogue: normalize, pack to single fp16 for 1-term out-projection
    float i0 = 1.f / l0, i1 = 1.f / l1;
    int b = bh >> 4, h = bh & 15;
    int r0 = b * N_ + qb * 128 + w * 16 + (lane >> 2);
#pragma unroll
    for (int nd = 0; nd < 8; nd++) {
        int col = h * 64 + nd * 8 + 2 * (lane & 3);
        *(uint32_t*)(Of + (size_t)r0 * E_ + col) = pack2h(o[nd][0] * i0, o[nd][1] * i0);
        *(uint32_t*)(Of + (size_t)(r0 + 8) * E_ + col) = pack2h(o[nd][2] * i1, o[nd][3] * i1);
    }
}

// ---------------------------------------------------------------------------
extern "C" void kernel_launch(void* const* d_in, const int* in_sizes, int n_in,
                              void* d_out, int out_size) {
    (void)in_sizes; (void)n_in; (void)out_size;
    const float* x     = (const float*)d_in[0];
    const float* W_qkv = (const float*)d_in[1];
    const float* b_qkv = (const float*)d_in[2];
    const float* W_out = (const float*)d_in[3];
    const float* b_out = (const float*)d_in[4];
    float* out = (float*)d_out;

    __half *wq, *wo, *xf, *qkv, *q_f, *k_f, *v_t, *o_f;
    cudaGetSymbolAddress((void**)&wq, g_wqkv);
    cudaGetSymbolAddress((void**)&wo, g_wout);
    cudaGetSymbolAddress((void**)&xf, g_xf);
    cudaGetSymbolAddress((void**)&qkv, g_qkv);
    cudaGetSymbolAddress((void**)&q_f, g_qf);
    cudaGetSymbolAddress((void**)&k_f, g_kf);
    cudaGetSymbolAddress((void**)&v_t, g_vt);
    cudaGetSymbolAddress((void**)&o_f, g_of);

    // Prep: cast x to fp16, transpose both weights to fp16
    cast_x_kernel<<<(M_TOT * E_ / 4 + 255) / 256, 256>>>((const float4*)x, xf,
                                                         M_TOT * E_ / 4);
    transpose_f16_kernel<<<dim3(QKV_N / 32, E_ / 32), 256>>>(W_qkv, wq, E_, QKV_N);
    transpose_f16_kernel<<<dim3(E_ / 32, E_ / 32), 256>>>(W_out, wo, E_, E_);

    // QKV projection (single-term fp16, fp16 out, 3-stage pipe)
    gemm_1t_h_kernel<<<dim3(QKV_N / 128, M_TOT / 128), 256>>>(
        xf, wq, b_qkv, qkv, M_TOT, QKV_N, E_);

    // Repack into per-head fp16 layouts
    repack_kernel<<<dim3(N_ / 64, BH_), 256>>>(qkv, q_f, k_f, v_t);

    // Attention
    attn_kernel<<<dim3(N_ / 128, BH_), 256>>>(q_f, k_f, v_t, o_f);

    // Output projection (single-term fp16, f32 out, 3-stage pipe)
    gemm_1t_kernel<<<dim3(E_ / 128, M_TOT / 128), 256>>>(
        o_f, wo, b_out, out, M_TOT, E_, E_);
}